// round 4
// baseline (speedup 1.0000x reference)
#include <cuda_runtime.h>
#include <cuda_bf16.h>
#include <cstdint>

#define BB 4
#define SS 2048
#define DD 1024
#define HH 16
#define HD 64
#define MR (BB*SS)

// split-bf16 scratch: value = hi + lo (lo = bf16 residual of f32)
__device__ __align__(256) __nv_bfloat16 g_xh [MR*DD],   g_xl [MR*DD];
__device__ __align__(256) __nv_bfloat16 g_ch [MR*DD],   g_cl [MR*DD];
__device__ __align__(256) __nv_bfloat16 g_Wqh[DD*DD],   g_Wql[DD*DD];
__device__ __align__(256) __nv_bfloat16 g_Wkh[DD*2*DD], g_Wkl[DD*2*DD];
__device__ __align__(256) __nv_bfloat16 g_Wph[DD*DD],   g_Wpl[DD*DD];
__device__ __align__(256) __nv_bfloat16 g_qh [MR*DD],   g_ql [MR*DD];   // [B,H,S,HD]
__device__ __align__(256) __nv_bfloat16 g_kh [MR*DD],   g_kl [MR*DD];
__device__ __align__(256) __nv_bfloat16 g_vh [MR*DD],   g_vl [MR*DD];
__device__ __align__(256) __nv_bfloat16 g_aoh[MR*DD],   g_aol[MR*DD];   // [B,S,D]

__device__ __forceinline__ void mma16816(float* c, const uint32_t* a, uint32_t b0, uint32_t b1) {
    asm volatile(
        "mma.sync.aligned.m16n8k16.row.col.f32.bf16.bf16.f32 "
        "{%0,%1,%2,%3}, {%4,%5,%6,%7}, {%8,%9}, {%0,%1,%2,%3};\n"
        : "+f"(c[0]), "+f"(c[1]), "+f"(c[2]), "+f"(c[3])
        : "r"(a[0]), "r"(a[1]), "r"(a[2]), "r"(a[3]), "r"(b0), "r"(b1));
}

__device__ __forceinline__ uint32_t packbf2(float lo, float hi) {
    __nv_bfloat162 t;
    t.x = __float2bfloat16(lo);
    t.y = __float2bfloat16(hi);
    return *reinterpret_cast<uint32_t*>(&t);
}

__device__ __forceinline__ void split1(float v, __nv_bfloat16& h, __nv_bfloat16& l) {
    h = __float2bfloat16(v);
    l = __float2bfloat16(v - __bfloat162float(h));
}

__global__ void f2b_split_kernel(const float* __restrict__ in,
                                 __nv_bfloat16* __restrict__ oh,
                                 __nv_bfloat16* __restrict__ ol, int n) {
    int i = (blockIdx.x * blockDim.x + threadIdx.x) * 4;
    if (i >= n) return;
    float4 v = *(const float4*)(in + i);
    __nv_bfloat162 h0, h1, l0, l1;
    split1(v.x, h0.x, l0.x); split1(v.y, h0.y, l0.y);
    split1(v.z, h1.x, l1.x); split1(v.w, h1.y, l1.y);
    *(__nv_bfloat162*)(oh + i)     = h0;
    *(__nv_bfloat162*)(oh + i + 2) = h1;
    *(__nv_bfloat162*)(ol + i)     = l0;
    *(__nv_bfloat162*)(ol + i + 2) = l1;
}

// EPI 0: Q proj + RMSNorm*gq*0.125 -> q hi/lo [B,H,S,HD]
// EPI 1: KV proj; K half RMSNorm*gk -> k hi/lo, V half -> v hi/lo
// EPI 2: out proj + bias -> f32 out
template<int EPI>
__global__ __launch_bounds__(256) void gemm_epi(
    const __nv_bfloat16* __restrict__ Ah,
    const __nv_bfloat16* __restrict__ Al,
    const __nv_bfloat16* __restrict__ Wh,
    const __nv_bfloat16* __restrict__ Wl,
    const float* __restrict__ bias,
    const float* __restrict__ gvec,
    int N,
    __nv_bfloat16* __restrict__ o0h, __nv_bfloat16* __restrict__ o0l,
    __nv_bfloat16* __restrict__ o1h, __nv_bfloat16* __restrict__ o1l,
    float* __restrict__ outf)
{
    __shared__ __align__(16) union SMem {
        struct {
            __nv_bfloat16 Ah[128][40], Al[128][40];
            __nv_bfloat16 Bh[32][72],  Bl[32][72];
        } gm;
        float epi[128][65];
    } sm;
    __shared__ float invs[128];

    const int tid  = threadIdx.x;
    const int warp = tid >> 5, lane = tid & 31;
    const int wm = warp >> 1, wn = warp & 1;
    const int g = lane >> 2, tg = lane & 3;
    const int n0 = blockIdx.x * 64;
    const int m0 = blockIdx.y * 128;

    float c[2][4][4];
#pragma unroll
    for (int i = 0; i < 2; i++)
#pragma unroll
        for (int j = 0; j < 4; j++)
#pragma unroll
            for (int k = 0; k < 4; k++) c[i][j][k] = 0.f;

    for (int k0 = 0; k0 < 1024; k0 += 32) {
        __syncthreads();
#pragma unroll
        for (int it = 0; it < 2; it++) {
            int cidx = tid + it * 256;
            int r = cidx >> 2, cc = (cidx & 3) * 8;
            size_t go = (size_t)(m0 + r) * 1024 + k0 + cc;
            *(uint4*)&sm.gm.Ah[r][cc] = *(const uint4*)(Ah + go);
            *(uint4*)&sm.gm.Al[r][cc] = *(const uint4*)(Al + go);
        }
        {
            int r = tid >> 3, cc = (tid & 7) * 8;
            size_t go = (size_t)(k0 + r) * N + n0 + cc;
            *(uint4*)&sm.gm.Bh[r][cc] = *(const uint4*)(Wh + go);
            *(uint4*)&sm.gm.Bl[r][cc] = *(const uint4*)(Wl + go);
        }
        __syncthreads();
#pragma unroll
        for (int kc = 0; kc < 2; kc++) {
            uint32_t ah[2][4], al[2][4], bh[4][2], bl[4][2];
#pragma unroll
            for (int mt = 0; mt < 2; mt++) {
                int r = wm * 32 + mt * 16 + g;
                int col = kc * 16 + 2 * tg;
                ah[mt][0] = *(const uint32_t*)&sm.gm.Ah[r][col];
                ah[mt][1] = *(const uint32_t*)&sm.gm.Ah[r + 8][col];
                ah[mt][2] = *(const uint32_t*)&sm.gm.Ah[r][col + 8];
                ah[mt][3] = *(const uint32_t*)&sm.gm.Ah[r + 8][col + 8];
                al[mt][0] = *(const uint32_t*)&sm.gm.Al[r][col];
                al[mt][1] = *(const uint32_t*)&sm.gm.Al[r + 8][col];
                al[mt][2] = *(const uint32_t*)&sm.gm.Al[r][col + 8];
                al[mt][3] = *(const uint32_t*)&sm.gm.Al[r + 8][col + 8];
            }
#pragma unroll
            for (int nt = 0; nt < 4; nt++) {
                int n = wn * 32 + nt * 8 + g;
                int kk = kc * 16 + 2 * tg;
                uint32_t lo = *(const unsigned short*)&sm.gm.Bh[kk][n];
                uint32_t hi = *(const unsigned short*)&sm.gm.Bh[kk + 1][n];
                bh[nt][0] = lo | (hi << 16);
                lo = *(const unsigned short*)&sm.gm.Bh[kk + 8][n];
                hi = *(const unsigned short*)&sm.gm.Bh[kk + 9][n];
                bh[nt][1] = lo | (hi << 16);
                lo = *(const unsigned short*)&sm.gm.Bl[kk][n];
                hi = *(const unsigned short*)&sm.gm.Bl[kk + 1][n];
                bl[nt][0] = lo | (hi << 16);
                lo = *(const unsigned short*)&sm.gm.Bl[kk + 8][n];
                hi = *(const unsigned short*)&sm.gm.Bl[kk + 9][n];
                bl[nt][1] = lo | (hi << 16);
            }
#pragma unroll
            for (int mt = 0; mt < 2; mt++)
#pragma unroll
                for (int nt = 0; nt < 4; nt++) {
                    mma16816(c[mt][nt], ah[mt], bh[nt][0], bh[nt][1]);
                    mma16816(c[mt][nt], ah[mt], bl[nt][0], bl[nt][1]);
                    mma16816(c[mt][nt], al[mt], bh[nt][0], bh[nt][1]);
                }
        }
    }
    __syncthreads();
#pragma unroll
    for (int mt = 0; mt < 2; mt++)
#pragma unroll
        for (int nt = 0; nt < 4; nt++) {
            int r = wm * 32 + mt * 16 + g, col = wn * 32 + nt * 8 + 2 * tg;
            sm.epi[r][col]         = c[mt][nt][0];
            sm.epi[r][col + 1]     = c[mt][nt][1];
            sm.epi[r + 8][col]     = c[mt][nt][2];
            sm.epi[r + 8][col + 1] = c[mt][nt][3];
        }
    __syncthreads();

    if (EPI == 2) {
#pragma unroll 4
        for (int idx = tid; idx < 128 * 64; idx += 256) {
            int r = idx >> 6, i = idx & 63;
            outf[(size_t)(m0 + r) * 1024 + n0 + i] = sm.epi[r][i] + bias[n0 + i];
        }
        return;
    }

    const bool doNorm = (EPI == 0) || (blockIdx.x < 16);
    if (tid < 128) {
        if (doNorm) {
            float ss = 0.f;
#pragma unroll 8
            for (int i = 0; i < 64; i++) {
                float v = sm.epi[tid][i] + bias[n0 + i];
                ss += v * v;
            }
            invs[tid] = rsqrtf(ss * (1.0f / 64.0f) + 1e-6f);
        } else {
            invs[tid] = 1.f;
        }
    }
    __syncthreads();

    const int bidx = m0 >> 11;
    const int s0   = m0 & 2047;
    int h;
    __nv_bfloat16 *dh, *dl;
    if (EPI == 0) { h = blockIdx.x; dh = o0h; dl = o0l; }
    else {
        h = blockIdx.x & 15;
        if (blockIdx.x < 16) { dh = o0h; dl = o0l; }
        else                 { dh = o1h; dl = o1l; }
    }

#pragma unroll 4
    for (int idx = tid; idx < 128 * 64; idx += 256) {
        int r = idx >> 6, i = idx & 63;
        float v = sm.epi[r][i] + bias[n0 + i];
        float w;
        if (EPI == 0)    w = v * invs[r] * gvec[i] * 0.125f;
        else if (doNorm) w = v * invs[r] * gvec[i];
        else             w = v;
        size_t off = ((size_t)(bidx * HH + h) * 2048 + s0 + r) * 64 + i;
        __nv_bfloat16 hh, ll;
        split1(w, hh, ll);
        dh[off] = hh;
        dl[off] = ll;
    }
}

__global__ __launch_bounds__(128) void attn_kernel(
    const __nv_bfloat16* __restrict__ Qh, const __nv_bfloat16* __restrict__ Ql,
    const __nv_bfloat16* __restrict__ Kh, const __nv_bfloat16* __restrict__ Kl,
    const __nv_bfloat16* __restrict__ Vh, const __nv_bfloat16* __restrict__ Vl,
    __nv_bfloat16* __restrict__ Oh, __nv_bfloat16* __restrict__ Ol)
{
    // 4 tiles only (36 KB). Q is staged through ksh/ksl in the prologue,
    // extracted to registers, then the buffers are reused for K/V tiles.
    __shared__ __align__(16) __nv_bfloat16 ksh[64][72], ksl[64][72];
    __shared__ __align__(16) __nv_bfloat16 vsh[64][72], vsl[64][72];

    const int tid = threadIdx.x, w = tid >> 5, lane = tid & 31;
    const int g = lane >> 2, tg = lane & 3;
    const int qt = blockIdx.x, h = blockIdx.y, b = blockIdx.z;
    const int bh = b * HH + h;

    const size_t qoff = ((size_t)bh * SS + qt * 64) * 64;
    const size_t koff = (size_t)bh * SS * 64;

    // stage Q through the K buffers
#pragma unroll
    for (int it = 0; it < 4; it++) {
        int cidx = it * 128 + tid;
        int r = cidx >> 3, cc = (cidx & 7) * 8;
        *(uint4*)&ksh[r][cc] = *(const uint4*)(Qh + qoff + cidx * 8);
        *(uint4*)&ksl[r][cc] = *(const uint4*)(Ql + qoff + cidx * 8);
    }
    __syncthreads();

    uint32_t aqh[4][4], aql[4][4];
#pragma unroll
    for (int kc = 0; kc < 4; kc++) {
        int r = w * 16 + g;
        int col = kc * 16 + 2 * tg;
        aqh[kc][0] = *(const uint32_t*)&ksh[r][col];
        aqh[kc][1] = *(const uint32_t*)&ksh[r + 8][col];
        aqh[kc][2] = *(const uint32_t*)&ksh[r][col + 8];
        aqh[kc][3] = *(const uint32_t*)&ksh[r + 8][col + 8];
        aql[kc][0] = *(const uint32_t*)&ksl[r][col];
        aql[kc][1] = *(const uint32_t*)&ksl[r + 8][col];
        aql[kc][2] = *(const uint32_t*)&ksl[r][col + 8];
        aql[kc][3] = *(const uint32_t*)&ksl[r + 8][col + 8];
    }

    float oacc[8][4];
#pragma unroll
    for (int nt = 0; nt < 8; nt++)
#pragma unroll
        for (int i = 0; i < 4; i++) oacc[nt][i] = 0.f;
    float mrow0 = -1e30f, mrow1 = -1e30f;
    float lrow0 = 0.f, lrow1 = 0.f;

    for (int j = 0; j < SS / 64; j++) {
        __syncthreads();
#pragma unroll
        for (int it = 0; it < 4; it++) {
            int cidx = it * 128 + tid;
            int r = cidx >> 3, cc = (cidx & 7) * 8;
            size_t go = koff + j * 4096 + cidx * 8;
            *(uint4*)&ksh[r][cc] = *(const uint4*)(Kh + go);
            *(uint4*)&ksl[r][cc] = *(const uint4*)(Kl + go);
            *(uint4*)&vsh[r][cc] = *(const uint4*)(Vh + go);
            *(uint4*)&vsl[r][cc] = *(const uint4*)(Vl + go);
        }
        __syncthreads();

        // S = q @ k^T split: qh*kh + qh*kl + ql*kh
        float sf[8][4];
#pragma unroll
        for (int nt = 0; nt < 8; nt++) {
#pragma unroll
            for (int i = 0; i < 4; i++) sf[nt][i] = 0.f;
#pragma unroll
            for (int kc = 0; kc < 4; kc++) {
                int col = kc * 16 + 2 * tg;
                int rr = nt * 8 + g;
                uint32_t bh0 = *(const uint32_t*)&ksh[rr][col];
                uint32_t bh1 = *(const uint32_t*)&ksh[rr][col + 8];
                uint32_t bl0 = *(const uint32_t*)&ksl[rr][col];
                uint32_t bl1 = *(const uint32_t*)&ksl[rr][col + 8];
                mma16816(sf[nt], aqh[kc], bh0, bh1);
                mma16816(sf[nt], aqh[kc], bl0, bl1);
                mma16816(sf[nt], aql[kc], bh0, bh1);
            }
        }

        float mn0 = mrow0, mn1 = mrow1;
#pragma unroll
        for (int nt = 0; nt < 8; nt++) {
            mn0 = fmaxf(mn0, fmaxf(sf[nt][0], sf[nt][1]));
            mn1 = fmaxf(mn1, fmaxf(sf[nt][2], sf[nt][3]));
        }
        mn0 = fmaxf(mn0, __shfl_xor_sync(0xffffffffu, mn0, 1));
        mn0 = fmaxf(mn0, __shfl_xor_sync(0xffffffffu, mn0, 2));
        mn1 = fmaxf(mn1, __shfl_xor_sync(0xffffffffu, mn1, 1));
        mn1 = fmaxf(mn1, __shfl_xor_sync(0xffffffffu, mn1, 2));

        float alpha0 = __expf(mrow0 - mn0);
        float alpha1 = __expf(mrow1 - mn1);
        mrow0 = mn0; mrow1 = mn1;

        float ps0 = 0.f, ps1 = 0.f;
#pragma unroll
        for (int nt = 0; nt < 8; nt++) {
            sf[nt][0] = __expf(sf[nt][0] - mn0);
            sf[nt][1] = __expf(sf[nt][1] - mn0);
            sf[nt][2] = __expf(sf[nt][2] - mn1);
            sf[nt][3] = __expf(sf[nt][3] - mn1);
            ps0 += sf[nt][0] + sf[nt][1];
            ps1 += sf[nt][2] + sf[nt][3];
        }
        lrow0 = lrow0 * alpha0 + ps0;
        lrow1 = lrow1 * alpha1 + ps1;

        // split P into hi + lo A-fragments
        uint32_t pah[4][4], pal[4][4];
#pragma unroll
        for (int kc = 0; kc < 4; kc++) {
#pragma unroll
            for (int q2 = 0; q2 < 2; q2++) {
                float f0 = sf[2 * kc + q2][0], f1 = sf[2 * kc + q2][1];
                float f2 = sf[2 * kc + q2][2], f3 = sf[2 * kc + q2][3];
                uint32_t h01 = packbf2(f0, f1);
                uint32_t h23 = packbf2(f2, f3);
                __nv_bfloat162 hb01 = *reinterpret_cast<__nv_bfloat162*>(&h01);
                __nv_bfloat162 hb23 = *reinterpret_cast<__nv_bfloat162*>(&h23);
                uint32_t l01 = packbf2(f0 - __bfloat162float(hb01.x), f1 - __bfloat162float(hb01.y));
                uint32_t l23 = packbf2(f2 - __bfloat162float(hb23.x), f3 - __bfloat162float(hb23.y));
                pah[kc][q2 * 2]     = h01;
                pah[kc][q2 * 2 + 1] = h23;
                pal[kc][q2 * 2]     = l01;
                pal[kc][q2 * 2 + 1] = l23;
            }
        }

#pragma unroll
        for (int nt = 0; nt < 8; nt++) {
            oacc[nt][0] *= alpha0; oacc[nt][1] *= alpha0;
            oacc[nt][2] *= alpha1; oacc[nt][3] *= alpha1;
        }

        // O += P @ V split: ph*vh + ph*vl + pl*vh
#pragma unroll
        for (int nt = 0; nt < 8; nt++) {
            int d = nt * 8 + g;
#pragma unroll
            for (int kc = 0; kc < 4; kc++) {
                int t0 = kc * 16 + 2 * tg;
                uint32_t lo = *(const unsigned short*)&vsh[t0][d];
                uint32_t hi = *(const unsigned short*)&vsh[t0 + 1][d];
                uint32_t bh0 = lo | (hi << 16);
                lo = *(const unsigned short*)&vsh[t0 + 8][d];
                hi = *(const unsigned short*)&vsh[t0 + 9][d];
                uint32_t bh1 = lo | (hi << 16);
                lo = *(const unsigned short*)&vsl[t0][d];
                hi = *(const unsigned short*)&vsl[t0 + 1][d];
                uint32_t bl0 = lo | (hi << 16);
                lo = *(const unsigned short*)&vsl[t0 + 8][d];
                hi = *(const unsigned short*)&vsl[t0 + 9][d];
                uint32_t bl1 = lo | (hi << 16);
                mma16816(oacc[nt], pah[kc], bh0, bh1);
                mma16816(oacc[nt], pah[kc], bl0, bl1);
                mma16816(oacc[nt], pal[kc], bh0, bh1);
            }
        }
    }

    lrow0 += __shfl_xor_sync(0xffffffffu, lrow0, 1);
    lrow0 += __shfl_xor_sync(0xffffffffu, lrow0, 2);
    lrow1 += __shfl_xor_sync(0xffffffffu, lrow1, 1);
    lrow1 += __shfl_xor_sync(0xffffffffu, lrow1, 2);
    float i0 = 1.f / lrow0;
    float i1 = 1.f / lrow1;

    const int srow = qt * 64 + w * 16 + g;
    size_t base = ((size_t)b * SS + srow) * 1024 + h * 64;
#pragma unroll
    for (int nt = 0; nt < 8; nt++) {
        int col = nt * 8 + 2 * tg;
        float f0 = oacc[nt][0] * i0, f1 = oacc[nt][1] * i0;
        float f2 = oacc[nt][2] * i1, f3 = oacc[nt][3] * i1;
        uint32_t h01 = packbf2(f0, f1);
        uint32_t h23 = packbf2(f2, f3);
        __nv_bfloat162 hb01 = *reinterpret_cast<__nv_bfloat162*>(&h01);
        __nv_bfloat162 hb23 = *reinterpret_cast<__nv_bfloat162*>(&h23);
        uint32_t l01 = packbf2(f0 - __bfloat162float(hb01.x), f1 - __bfloat162float(hb01.y));
        uint32_t l23 = packbf2(f2 - __bfloat162float(hb23.x), f3 - __bfloat162float(hb23.y));
        *(uint32_t*)(Oh + base + col)            = h01;
        *(uint32_t*)(Ol + base + col)            = l01;
        *(uint32_t*)(Oh + base + 8 * 1024 + col) = h23;
        *(uint32_t*)(Ol + base + 8 * 1024 + col) = l23;
    }
}

extern "C" void kernel_launch(void* const* d_in, const int* in_sizes, int n_in,
                              void* d_out, int out_size)
{
    const float* x     = (const float*)d_in[0];
    const float* ctx   = (const float*)d_in[1];
    const float* Wq    = (const float*)d_in[2];
    const float* bq    = (const float*)d_in[3];
    const float* Wkv   = (const float*)d_in[4];
    const float* bkv   = (const float*)d_in[5];
    const float* Wproj = (const float*)d_in[6];
    const float* bproj = (const float*)d_in[7];
    const float* gq    = (const float*)d_in[8];
    const float* gk    = (const float*)d_in[9];

    __nv_bfloat16 *xh, *xl, *ch, *cl, *wqh, *wql, *wkh, *wkl, *wph, *wpl;
    __nv_bfloat16 *qh, *ql, *kh, *kl, *vh, *vl, *aoh, *aol;
    cudaGetSymbolAddress((void**)&xh,  g_xh);  cudaGetSymbolAddress((void**)&xl,  g_xl);
    cudaGetSymbolAddress((void**)&ch,  g_ch);  cudaGetSymbolAddress((void**)&cl,  g_cl);
    cudaGetSymbolAddress((void**)&wqh, g_Wqh); cudaGetSymbolAddress((void**)&wql, g_Wql);
    cudaGetSymbolAddress((void**)&wkh, g_Wkh); cudaGetSymbolAddress((void**)&wkl, g_Wkl);
    cudaGetSymbolAddress((void**)&wph, g_Wph); cudaGetSymbolAddress((void**)&wpl, g_Wpl);
    cudaGetSymbolAddress((void**)&qh,  g_qh);  cudaGetSymbolAddress((void**)&ql,  g_ql);
    cudaGetSymbolAddress((void**)&kh,  g_kh);  cudaGetSymbolAddress((void**)&kl,  g_kl);
    cudaGetSymbolAddress((void**)&vh,  g_vh);  cudaGetSymbolAddress((void**)&vl,  g_vl);
    cudaGetSymbolAddress((void**)&aoh, g_aoh); cudaGetSymbolAddress((void**)&aol, g_aol);

    f2b_split_kernel<<<MR * DD / 1024, 256>>>(x,     xh,  xl,  MR * DD);
    f2b_split_kernel<<<MR * DD / 1024, 256>>>(ctx,   ch,  cl,  MR * DD);
    f2b_split_kernel<<<DD * DD / 1024, 256>>>(Wq,    wqh, wql, DD * DD);
    f2b_split_kernel<<<DD * 2 * DD / 1024, 256>>>(Wkv, wkh, wkl, DD * 2 * DD);
    f2b_split_kernel<<<DD * DD / 1024, 256>>>(Wproj, wph, wpl, DD * DD);

    gemm_epi<0><<<dim3(16, 64), 256>>>(xh, xl, wqh, wql, bq, gq, 1024,
                                       qh, ql, nullptr, nullptr, nullptr);
    gemm_epi<1><<<dim3(32, 64), 256>>>(ch, cl, wkh, wkl, bkv, gk, 2048,
                                       kh, kl, vh, vl, nullptr);
    attn_kernel<<<dim3(32, 16, 4), 128>>>(qh, ql, kh, kl, vh, vl, aoh, aol);
    gemm_epi<2><<<dim3(16, 64), 256>>>(aoh, aol, wph, wpl, bproj, nullptr, 1024,
                                       nullptr, nullptr, nullptr, nullptr, (float*)d_out);
}

// round 6
// speedup vs baseline: 1.0468x; 1.0468x over previous
#include <cuda_runtime.h>
#include <cuda_bf16.h>
#include <cstdint>

#define BB 4
#define SS 2048
#define DD 1024
#define HH 16
#define HD 64
#define MR (BB*SS)

// split-bf16 scratch: value = hi + lo (lo = bf16 residual of f32)
__device__ __align__(256) __nv_bfloat16 g_xh [MR*DD],   g_xl [MR*DD];
__device__ __align__(256) __nv_bfloat16 g_ch [MR*DD],   g_cl [MR*DD];
__device__ __align__(256) __nv_bfloat16 g_Wqh[DD*DD],   g_Wql[DD*DD];     // transposed [N][K]
__device__ __align__(256) __nv_bfloat16 g_Wkh[DD*2*DD], g_Wkl[DD*2*DD];   // transposed [2N][K]
__device__ __align__(256) __nv_bfloat16 g_Wph[DD*DD],   g_Wpl[DD*DD];     // transposed [N][K]
__device__ __align__(256) __nv_bfloat16 g_qh [MR*DD],   g_ql [MR*DD];     // [B,H,S,HD]
__device__ __align__(256) __nv_bfloat16 g_kh [MR*DD],   g_kl [MR*DD];     // [B,H,Sc,HD]
__device__ __align__(256) __nv_bfloat16 g_vth[MR*DD],   g_vtl[MR*DD];     // transposed [B,H,HD,Sc]
__device__ __align__(256) __nv_bfloat16 g_aoh[MR*DD],   g_aol[MR*DD];     // [B,S,D]

__device__ __forceinline__ void mma16816(float* c, const uint32_t* a, uint32_t b0, uint32_t b1) {
    asm volatile(
        "mma.sync.aligned.m16n8k16.row.col.f32.bf16.bf16.f32 "
        "{%0,%1,%2,%3}, {%4,%5,%6,%7}, {%8,%9}, {%0,%1,%2,%3};\n"
        : "+f"(c[0]), "+f"(c[1]), "+f"(c[2]), "+f"(c[3])
        : "r"(a[0]), "r"(a[1]), "r"(a[2]), "r"(a[3]), "r"(b0), "r"(b1));
}

__device__ __forceinline__ uint32_t packbf2(float lo, float hi) {
    __nv_bfloat162 t;
    t.x = __float2bfloat16(lo);
    t.y = __float2bfloat16(hi);
    return *reinterpret_cast<uint32_t*>(&t);
}

__device__ __forceinline__ void split1(float v, __nv_bfloat16& h, __nv_bfloat16& l) {
    h = __float2bfloat16(v);
    l = __float2bfloat16(v - __bfloat162float(h));
}

__device__ __forceinline__ void cpa16(uint32_t saddr, const void* g) {
    asm volatile("cp.async.cg.shared.global [%0], [%1], 16;\n" :: "r"(saddr), "l"(g));
}

// ---------------- converts ----------------
__global__ void f2b_split_kernel(const float* __restrict__ in,
                                 __nv_bfloat16* __restrict__ oh,
                                 __nv_bfloat16* __restrict__ ol, int n) {
    int i = (blockIdx.x * blockDim.x + threadIdx.x) * 4;
    if (i >= n) return;
    float4 v = *(const float4*)(in + i);
    __nv_bfloat162 h0, h1, l0, l1;
    split1(v.x, h0.x, l0.x); split1(v.y, h0.y, l0.y);
    split1(v.z, h1.x, l1.x); split1(v.w, h1.y, l1.y);
    *(__nv_bfloat162*)(oh + i)     = h0;
    *(__nv_bfloat162*)(oh + i + 2) = h1;
    *(__nv_bfloat162*)(ol + i)     = l0;
    *(__nv_bfloat162*)(ol + i + 2) = l1;
}

// convert + transpose: in f32 [K][N] -> out bf16 hi/lo [N][K]
__global__ __launch_bounds__(256) void f2b_split_T_kernel(
    const float* __restrict__ in,
    __nv_bfloat16* __restrict__ oh,
    __nv_bfloat16* __restrict__ ol, int K, int N)
{
    __shared__ float t[32][33];
    int n0 = blockIdx.x * 32, k0 = blockIdx.y * 32;
    int r = threadIdx.x >> 3, c4 = (threadIdx.x & 7) * 4;
    float4 v = *(const float4*)(in + (size_t)(k0 + r) * N + n0 + c4);
    t[r][c4] = v.x; t[r][c4 + 1] = v.y; t[r][c4 + 2] = v.z; t[r][c4 + 3] = v.w;
    __syncthreads();
    union { __nv_bfloat16 b[4]; uint2 u; } H, L;
#pragma unroll
    for (int i = 0; i < 4; i++) split1(t[c4 + i][r], H.b[i], L.b[i]);
    size_t off = (size_t)(n0 + r) * K + k0 + c4;
    *(uint2*)(oh + off) = H.u;
    *(uint2*)(ol + off) = L.u;
}

// ---------------- GEMM with fused epilogues ----------------
// Weights are pre-transposed: Wt[N][K]. B-tile stored [n][k] in smem -> 32-bit fragment LDS.
// EPI 0: Q proj + RMSNorm*gq*0.125 -> q hi/lo [B,H,S,HD]
// EPI 1: KV proj; K half RMSNorm*gk -> k hi/lo [B,H,Sc,HD]; V half -> TRANSPOSED v hi/lo [B,H,HD,Sc]
// EPI 2: out proj + bias -> f32 out
template<int EPI>
__global__ __launch_bounds__(256) void gemm_epi(
    const __nv_bfloat16* __restrict__ Ah,
    const __nv_bfloat16* __restrict__ Al,
    const __nv_bfloat16* __restrict__ Wth,
    const __nv_bfloat16* __restrict__ Wtl,
    const float* __restrict__ bias,
    const float* __restrict__ gvec,
    __nv_bfloat16* __restrict__ o0h, __nv_bfloat16* __restrict__ o0l,
    __nv_bfloat16* __restrict__ o1h, __nv_bfloat16* __restrict__ o1l,
    float* __restrict__ outf)
{
    __shared__ __align__(16) union SMem {
        struct {
            __nv_bfloat16 Ah[128][40], Al[128][40];
            __nv_bfloat16 Bh[64][40],  Bl[64][40];   // transposed: [n][k]
        } gm;
        float epi[128][65];
    } sm;
    __shared__ float invs[128];

    const int tid  = threadIdx.x;
    const int warp = tid >> 5, lane = tid & 31;
    const int wm = warp >> 1, wn = warp & 1;
    const int g = lane >> 2, tg = lane & 3;
    const int n0 = blockIdx.x * 64;
    const int m0 = blockIdx.y * 128;

    // per-thread copy indices
    const int a0r = tid >> 2, a1r = (tid + 256) >> 2, ac = (tid & 3) * 8;
    const int br = tid >> 2,  bc = (tid & 3) * 8;

    float c[2][4][4];
#pragma unroll
    for (int i = 0; i < 2; i++)
#pragma unroll
        for (int j = 0; j < 4; j++)
#pragma unroll
            for (int k = 0; k < 4; k++) c[i][j][k] = 0.f;

    // prefetch regs
    uint4 pAh0, pAh1, pAl0, pAl1, pBh, pBl;
    {
        size_t ga0 = (size_t)(m0 + a0r) * 1024 + ac;
        size_t ga1 = (size_t)(m0 + a1r) * 1024 + ac;
        size_t gb  = (size_t)(n0 + br) * 1024 + bc;
        pAh0 = *(const uint4*)(Ah + ga0);  pAh1 = *(const uint4*)(Ah + ga1);
        pAl0 = *(const uint4*)(Al + ga0);  pAl1 = *(const uint4*)(Al + ga1);
        pBh  = *(const uint4*)(Wth + gb);  pBl  = *(const uint4*)(Wtl + gb);
    }

    for (int k0 = 0; k0 < 1024; k0 += 32) {
        *(uint4*)&sm.gm.Ah[a0r][ac] = pAh0;
        *(uint4*)&sm.gm.Ah[a1r][ac] = pAh1;
        *(uint4*)&sm.gm.Al[a0r][ac] = pAl0;
        *(uint4*)&sm.gm.Al[a1r][ac] = pAl1;
        *(uint4*)&sm.gm.Bh[br][bc]  = pBh;
        *(uint4*)&sm.gm.Bl[br][bc]  = pBl;
        __syncthreads();

        if (k0 + 32 < 1024) {
            int kn = k0 + 32;
            size_t ga0 = (size_t)(m0 + a0r) * 1024 + kn + ac;
            size_t ga1 = (size_t)(m0 + a1r) * 1024 + kn + ac;
            size_t gb  = (size_t)(n0 + br) * 1024 + kn + bc;
            pAh0 = *(const uint4*)(Ah + ga0);  pAh1 = *(const uint4*)(Ah + ga1);
            pAl0 = *(const uint4*)(Al + ga0);  pAl1 = *(const uint4*)(Al + ga1);
            pBh  = *(const uint4*)(Wth + gb);  pBl  = *(const uint4*)(Wtl + gb);
        }

#pragma unroll
        for (int kc = 0; kc < 2; kc++) {
            uint32_t ah[2][4], al[2][4], bh[4][2], bl[4][2];
#pragma unroll
            for (int mt = 0; mt < 2; mt++) {
                int r = wm * 32 + mt * 16 + g;
                int col = kc * 16 + 2 * tg;
                ah[mt][0] = *(const uint32_t*)&sm.gm.Ah[r][col];
                ah[mt][1] = *(const uint32_t*)&sm.gm.Ah[r + 8][col];
                ah[mt][2] = *(const uint32_t*)&sm.gm.Ah[r][col + 8];
                ah[mt][3] = *(const uint32_t*)&sm.gm.Ah[r + 8][col + 8];
                al[mt][0] = *(const uint32_t*)&sm.gm.Al[r][col];
                al[mt][1] = *(const uint32_t*)&sm.gm.Al[r + 8][col];
                al[mt][2] = *(const uint32_t*)&sm.gm.Al[r][col + 8];
                al[mt][3] = *(const uint32_t*)&sm.gm.Al[r + 8][col + 8];
            }
#pragma unroll
            for (int nt = 0; nt < 4; nt++) {
                int n = wn * 32 + nt * 8 + g;
                int kk = kc * 16 + 2 * tg;
                bh[nt][0] = *(const uint32_t*)&sm.gm.Bh[n][kk];
                bh[nt][1] = *(const uint32_t*)&sm.gm.Bh[n][kk + 8];
                bl[nt][0] = *(const uint32_t*)&sm.gm.Bl[n][kk];
                bl[nt][1] = *(const uint32_t*)&sm.gm.Bl[n][kk + 8];
            }
#pragma unroll
            for (int mt = 0; mt < 2; mt++)
#pragma unroll
                for (int nt = 0; nt < 4; nt++) {
                    mma16816(c[mt][nt], ah[mt], bh[nt][0], bh[nt][1]);
                    mma16816(c[mt][nt], ah[mt], bl[nt][0], bl[nt][1]);
                    mma16816(c[mt][nt], al[mt], bh[nt][0], bh[nt][1]);
                }
        }
        __syncthreads();
    }

#pragma unroll
    for (int mt = 0; mt < 2; mt++)
#pragma unroll
        for (int nt = 0; nt < 4; nt++) {
            int r = wm * 32 + mt * 16 + g, col = wn * 32 + nt * 8 + 2 * tg;
            sm.epi[r][col]         = c[mt][nt][0];
            sm.epi[r][col + 1]     = c[mt][nt][1];
            sm.epi[r + 8][col]     = c[mt][nt][2];
            sm.epi[r + 8][col + 1] = c[mt][nt][3];
        }
    __syncthreads();

    if (EPI == 2) {
#pragma unroll 4
        for (int idx = tid; idx < 128 * 64; idx += 256) {
            int r = idx >> 6, i = idx & 63;
            outf[(size_t)(m0 + r) * 1024 + n0 + i] = sm.epi[r][i] + bias[n0 + i];
        }
        return;
    }

    const int bidx = m0 >> 11;
    const int s0   = m0 & 2047;

    if (EPI == 1 && blockIdx.x >= 16) {
        // V half: no norm, write TRANSPOSED [bh][d][s]
        const int h = blockIdx.x & 15;
        const size_t vbase = (size_t)(bidx * HH + h) * 64;
#pragma unroll 4
        for (int idx = tid; idx < 128 * 64; idx += 256) {
            int d = idx >> 7, r = idx & 127;
            float v = sm.epi[r][d] + bias[n0 + d];
            __nv_bfloat16 hh, ll;
            split1(v, hh, ll);
            size_t off = (vbase + d) * 2048 + s0 + r;
            o1h[off] = hh;
            o1l[off] = ll;
        }
        return;
    }

    // normed paths (EPI0 always, EPI1 K half)
    if (tid < 128) {
        float ss = 0.f;
#pragma unroll 8
        for (int i = 0; i < 64; i++) {
            float v = sm.epi[tid][i] + bias[n0 + i];
            ss += v * v;
        }
        invs[tid] = rsqrtf(ss * (1.0f / 64.0f) + 1e-6f);
    }
    __syncthreads();

    const int h = (EPI == 0) ? blockIdx.x : (blockIdx.x & 15);
    const float postmul = (EPI == 0) ? 0.125f : 1.0f;   // fold 1/sqrt(HD) into q
#pragma unroll 4
    for (int idx = tid; idx < 128 * 64; idx += 256) {
        int r = idx >> 6, i = idx & 63;
        float v = sm.epi[r][i] + bias[n0 + i];
        float w = v * invs[r] * gvec[i] * postmul;
        size_t off = ((size_t)(bidx * HH + h) * 2048 + s0 + r) * 64 + i;
        __nv_bfloat16 hh, ll;
        split1(w, hh, ll);
        o0h[off] = hh;
        o0l[off] = ll;
    }
}

// ---------------- flash attention: 256 thr, 128 q-rows/CTA, cp.async 2-stage ----------------
#define ATT_STG 36864   // bytes per stage: 4 tiles of 64*72*2
#define ATT_SMEM (2*ATT_STG)

__global__ __launch_bounds__(256, 1) void attn_kernel(
    const __nv_bfloat16* __restrict__ Qh, const __nv_bfloat16* __restrict__ Ql,
    const __nv_bfloat16* __restrict__ Kh, const __nv_bfloat16* __restrict__ Kl,
    const __nv_bfloat16* __restrict__ Vth, const __nv_bfloat16* __restrict__ Vtl,
    __nv_bfloat16* __restrict__ Oh, __nv_bfloat16* __restrict__ Ol)
{
    extern __shared__ __align__(16) char dynsmem[];
    const uint32_t sbase = (uint32_t)__cvta_generic_to_shared(dynsmem);

    const int tid = threadIdx.x, w = tid >> 5, lane = tid & 31;
    const int g = lane >> 2, tg = lane & 3;
    const int qt = blockIdx.x, h = blockIdx.y, b = blockIdx.z;
    const int bh = b * HH + h;

    const size_t koff = (size_t)bh * SS * 64;                 // K [bh][t][d]
    const size_t voff = (size_t)bh * 64 * 2048;               // Vt [bh][d][s]
    const size_t qoff = koff + (size_t)qt * 128 * 64;         // Q [bh][s][d]

    // copy indices: 512 16B-chunks per tensor, 2 per thread
    const int c0row = tid >> 3,        c0off = (tid & 7) * 8;
    const int c1row = (tid + 256) >> 3, c1off = c0off;

    // Q fragments direct from gmem (once per CTA)
    uint32_t aqh[4][4], aql[4][4];
    {
        const __nv_bfloat16* qg = Qh + qoff;
        const __nv_bfloat16* ql = Ql + qoff;
        int r = w * 16 + g;
#pragma unroll
        for (int kc = 0; kc < 4; kc++) {
            int col = kc * 16 + 2 * tg;
            aqh[kc][0] = *(const uint32_t*)(qg + r * 64 + col);
            aqh[kc][1] = *(const uint32_t*)(qg + (r + 8) * 64 + col);
            aqh[kc][2] = *(const uint32_t*)(qg + r * 64 + col + 8);
            aqh[kc][3] = *(const uint32_t*)(qg + (r + 8) * 64 + col + 8);
            aql[kc][0] = *(const uint32_t*)(ql + r * 64 + col);
            aql[kc][1] = *(const uint32_t*)(ql + (r + 8) * 64 + col);
            aql[kc][2] = *(const uint32_t*)(ql + r * 64 + col + 8);
            aql[kc][3] = *(const uint32_t*)(ql + (r + 8) * 64 + col + 8);
        }
    }

    float oacc[8][4];
#pragma unroll
    for (int nt = 0; nt < 8; nt++)
#pragma unroll
        for (int i = 0; i < 4; i++) oacc[nt][i] = 0.f;
    float mrow0 = -1e30f, mrow1 = -1e30f;
    float lrow0 = 0.f, lrow1 = 0.f;

    // issue tile j into stage st
    auto issue = [&](int j, int st) {
        uint32_t sb = sbase + st * ATT_STG;
        // chunk 0
        {
            uint32_t so = c0row * 144 + c0off * 2;
            const __nv_bfloat16* kgp = Kh + koff + j * 4096 + c0row * 64 + c0off;
            const __nv_bfloat16* klp = Kl + koff + j * 4096 + c0row * 64 + c0off;
            const __nv_bfloat16* vhp = Vth + voff + (size_t)c0row * 2048 + j * 64 + c0off;
            const __nv_bfloat16* vlp = Vtl + voff + (size_t)c0row * 2048 + j * 64 + c0off;
            cpa16(sb + so,         kgp);
            cpa16(sb + 9216 + so,  klp);
            cpa16(sb + 18432 + so, vhp);
            cpa16(sb + 27648 + so, vlp);
        }
        // chunk 1
        {
            uint32_t so = c1row * 144 + c1off * 2;
            const __nv_bfloat16* kgp = Kh + koff + j * 4096 + c1row * 64 + c1off;
            const __nv_bfloat16* klp = Kl + koff + j * 4096 + c1row * 64 + c1off;
            const __nv_bfloat16* vhp = Vth + voff + (size_t)(c1row - 32) * 2048 + 32 * 2048 + j * 64 + c1off;
            const __nv_bfloat16* vlp = Vtl + voff + (size_t)(c1row - 32) * 2048 + 32 * 2048 + j * 64 + c1off;
            cpa16(sb + so,         kgp);
            cpa16(sb + 9216 + so,  klp);
            cpa16(sb + 18432 + so, vhp);
            cpa16(sb + 27648 + so, vlp);
        }
    };

    issue(0, 0);
    asm volatile("cp.async.commit_group;\n");

    for (int j = 0; j < SS / 64; j++) {
        int st = j & 1;
        if (j + 1 < SS / 64) issue(j + 1, st ^ 1);
        asm volatile("cp.async.commit_group;\n");
        asm volatile("cp.async.wait_group 1;\n");
        __syncthreads();

        __nv_bfloat16 (*ksh)[72] = (__nv_bfloat16(*)[72])(dynsmem + st * ATT_STG);
        __nv_bfloat16 (*ksl)[72] = (__nv_bfloat16(*)[72])(dynsmem + st * ATT_STG + 9216);
        __nv_bfloat16 (*vsh)[72] = (__nv_bfloat16(*)[72])(dynsmem + st * ATT_STG + 18432);
        __nv_bfloat16 (*vsl)[72] = (__nv_bfloat16(*)[72])(dynsmem + st * ATT_STG + 27648);

        // S = q @ k^T split: qh*kh + qh*kl + ql*kh
        float sf[8][4];
#pragma unroll
        for (int nt = 0; nt < 8; nt++) {
#pragma unroll
            for (int i = 0; i < 4; i++) sf[nt][i] = 0.f;
#pragma unroll
            for (int kc = 0; kc < 4; kc++) {
                int col = kc * 16 + 2 * tg;
                int rr = nt * 8 + g;
                uint32_t bh0 = *(const uint32_t*)&ksh[rr][col];
                uint32_t bh1 = *(const uint32_t*)&ksh[rr][col + 8];
                uint32_t bl0 = *(const uint32_t*)&ksl[rr][col];
                uint32_t bl1 = *(const uint32_t*)&ksl[rr][col + 8];
                mma16816(sf[nt], aqh[kc], bh0, bh1);
                mma16816(sf[nt], aqh[kc], bl0, bl1);
                mma16816(sf[nt], aql[kc], bh0, bh1);
            }
        }

        float mn0 = mrow0, mn1 = mrow1;
#pragma unroll
        for (int nt = 0; nt < 8; nt++) {
            mn0 = fmaxf(mn0, fmaxf(sf[nt][0], sf[nt][1]));
            mn1 = fmaxf(mn1, fmaxf(sf[nt][2], sf[nt][3]));
        }
        mn0 = fmaxf(mn0, __shfl_xor_sync(0xffffffffu, mn0, 1));
        mn0 = fmaxf(mn0, __shfl_xor_sync(0xffffffffu, mn0, 2));
        mn1 = fmaxf(mn1, __shfl_xor_sync(0xffffffffu, mn1, 1));
        mn1 = fmaxf(mn1, __shfl_xor_sync(0xffffffffu, mn1, 2));

        float alpha0 = __expf(mrow0 - mn0);
        float alpha1 = __expf(mrow1 - mn1);
        mrow0 = mn0; mrow1 = mn1;

        float ps0 = 0.f, ps1 = 0.f;
#pragma unroll
        for (int nt = 0; nt < 8; nt++) {
            sf[nt][0] = __expf(sf[nt][0] - mn0);
            sf[nt][1] = __expf(sf[nt][1] - mn0);
            sf[nt][2] = __expf(sf[nt][2] - mn1);
            sf[nt][3] = __expf(sf[nt][3] - mn1);
            ps0 += sf[nt][0] + sf[nt][1];
            ps1 += sf[nt][2] + sf[nt][3];
        }
        lrow0 = lrow0 * alpha0 + ps0;
        lrow1 = lrow1 * alpha1 + ps1;

        uint32_t pah[4][4], pal[4][4];
#pragma unroll
        for (int kc = 0; kc < 4; kc++) {
#pragma unroll
            for (int q2 = 0; q2 < 2; q2++) {
                float f0 = sf[2 * kc + q2][0], f1 = sf[2 * kc + q2][1];
                float f2 = sf[2 * kc + q2][2], f3 = sf[2 * kc + q2][3];
                uint32_t h01 = packbf2(f0, f1);
                uint32_t h23 = packbf2(f2, f3);
                __nv_bfloat162 hb01 = *reinterpret_cast<__nv_bfloat162*>(&h01);
                __nv_bfloat162 hb23 = *reinterpret_cast<__nv_bfloat162*>(&h23);
                uint32_t l01 = packbf2(f0 - __bfloat162float(hb01.x), f1 - __bfloat162float(hb01.y));
                uint32_t l23 = packbf2(f2 - __bfloat162float(hb23.x), f3 - __bfloat162float(hb23.y));
                pah[kc][q2 * 2]     = h01;
                pah[kc][q2 * 2 + 1] = h23;
                pal[kc][q2 * 2]     = l01;
                pal[kc][q2 * 2 + 1] = l23;
            }
        }

#pragma unroll
        for (int nt = 0; nt < 8; nt++) {
            oacc[nt][0] *= alpha0; oacc[nt][1] *= alpha0;
            oacc[nt][2] *= alpha1; oacc[nt][3] *= alpha1;
        }

        // O += P @ V split (V transposed in smem -> 32-bit fragment loads)
#pragma unroll
        for (int nt = 0; nt < 8; nt++) {
            int d = nt * 8 + g;
#pragma unroll
            for (int kc = 0; kc < 4; kc++) {
                int t0 = kc * 16 + 2 * tg;
                uint32_t bh0 = *(const uint32_t*)&vsh[d][t0];
                uint32_t bh1 = *(const uint32_t*)&vsh[d][t0 + 8];
                uint32_t bl0 = *(const uint32_t*)&vsl[d][t0];
                uint32_t bl1 = *(const uint32_t*)&vsl[d][t0 + 8];
                mma16816(oacc[nt], pah[kc], bh0, bh1);
                mma16816(oacc[nt], pah[kc], bl0, bl1);
                mma16816(oacc[nt], pal[kc], bh0, bh1);
            }
        }
        __syncthreads();
    }

    lrow0 += __shfl_xor_sync(0xffffffffu, lrow0, 1);
    lrow0 += __shfl_xor_sync(0xffffffffu, lrow0, 2);
    lrow1 += __shfl_xor_sync(0xffffffffu, lrow1, 1);
    lrow1 += __shfl_xor_sync(0xffffffffu, lrow1, 2);
    float i0 = 1.f / lrow0;
    float i1 = 1.f / lrow1;

    const int srow = qt * 128 + w * 16 + g;
    size_t base = ((size_t)b * SS + srow) * 1024 + h * 64;
#pragma unroll
    for (int nt = 0; nt < 8; nt++) {
        int col = nt * 8 + 2 * tg;
        float f0 = oacc[nt][0] * i0, f1 = oacc[nt][1] * i0;
        float f2 = oacc[nt][2] * i1, f3 = oacc[nt][3] * i1;
        uint32_t h01 = packbf2(f0, f1);
        uint32_t h23 = packbf2(f2, f3);
        __nv_bfloat162 hb01 = *reinterpret_cast<__nv_bfloat162*>(&h01);
        __nv_bfloat162 hb23 = *reinterpret_cast<__nv_bfloat162*>(&h23);
        uint32_t l01 = packbf2(f0 - __bfloat162float(hb01.x), f1 - __bfloat162float(hb01.y));
        uint32_t l23 = packbf2(f2 - __bfloat162float(hb23.x), f3 - __bfloat162float(hb23.y));
        *(uint32_t*)(Oh + base + col)            = h01;
        *(uint32_t*)(Ol + base + col)            = l01;
        *(uint32_t*)(Oh + base + 8 * 1024 + col) = h23;
        *(uint32_t*)(Ol + base + 8 * 1024 + col) = l23;
    }
}

extern "C" void kernel_launch(void* const* d_in, const int* in_sizes, int n_in,
                              void* d_out, int out_size)
{
    const float* x     = (const float*)d_in[0];
    const float* ctx   = (const float*)d_in[1];
    const float* Wq    = (const float*)d_in[2];
    const float* bq    = (const float*)d_in[3];
    const float* Wkv   = (const float*)d_in[4];
    const float* bkv   = (const float*)d_in[5];
    const float* Wproj = (const float*)d_in[6];
    const float* bproj = (const float*)d_in[7];
    const float* gq    = (const float*)d_in[8];
    const float* gk    = (const float*)d_in[9];

    __nv_bfloat16 *xh, *xl, *ch, *cl, *wqh, *wql, *wkh, *wkl, *wph, *wpl;
    __nv_bfloat16 *qh, *ql, *kh, *kl, *vth, *vtl, *aoh, *aol;
    cudaGetSymbolAddress((void**)&xh,  g_xh);  cudaGetSymbolAddress((void**)&xl,  g_xl);
    cudaGetSymbolAddress((void**)&ch,  g_ch);  cudaGetSymbolAddress((void**)&cl,  g_cl);
    cudaGetSymbolAddress((void**)&wqh, g_Wqh); cudaGetSymbolAddress((void**)&wql, g_Wql);
    cudaGetSymbolAddress((void**)&wkh, g_Wkh); cudaGetSymbolAddress((void**)&wkl, g_Wkl);
    cudaGetSymbolAddress((void**)&wph, g_Wph); cudaGetSymbolAddress((void**)&wpl, g_Wpl);
    cudaGetSymbolAddress((void**)&qh,  g_qh);  cudaGetSymbolAddress((void**)&ql,  g_ql);
    cudaGetSymbolAddress((void**)&kh,  g_kh);  cudaGetSymbolAddress((void**)&kl,  g_kl);
    cudaGetSymbolAddress((void**)&vth, g_vth); cudaGetSymbolAddress((void**)&vtl, g_vtl);
    cudaGetSymbolAddress((void**)&aoh, g_aoh); cudaGetSymbolAddress((void**)&aol, g_aol);

    cudaFuncSetAttribute(attn_kernel, cudaFuncAttributeMaxDynamicSharedMemorySize, ATT_SMEM);

    f2b_split_kernel<<<MR * DD / 1024, 256>>>(x,   xh, xl, MR * DD);
    f2b_split_kernel<<<MR * DD / 1024, 256>>>(ctx, ch, cl, MR * DD);
    f2b_split_T_kernel<<<dim3(32, 32), 256>>>(Wq,    wqh, wql, 1024, 1024);
    f2b_split_T_kernel<<<dim3(64, 32), 256>>>(Wkv,   wkh, wkl, 1024, 2048);
    f2b_split_T_kernel<<<dim3(32, 32), 256>>>(Wproj, wph, wpl, 1024, 1024);

    gemm_epi<0><<<dim3(16, 64), 256>>>(xh, xl, wqh, wql, bq, gq,
                                       qh, ql, nullptr, nullptr, nullptr);
    gemm_epi<1><<<dim3(32, 64), 256>>>(ch, cl, wkh, wkl, bkv, gk,
                                       kh, kl, vth, vtl, nullptr);
    attn_kernel<<<dim3(16, 16, 4), 256, ATT_SMEM>>>(qh, ql, kh, kl, vth, vtl, aoh, aol);
    gemm_epi<2><<<dim3(16, 64), 256>>>(aoh, aol, wph, wpl, bproj, nullptr,
                                       nullptr, nullptr, nullptr, nullptr, (float*)d_out);
}

// round 8
// speedup vs baseline: 2.2591x; 2.1582x over previous
#include <cuda_runtime.h>
#include <cuda_fp16.h>
#include <cstdint>

#define BB 4
#define SS 2048
#define DD 1024
#define HH 16
#define HD 64
#define MR (BB*SS)

// fp16 scratch
__device__ __align__(256) __half g_x  [MR*DD];
__device__ __align__(256) __half g_c  [MR*DD];
__device__ __align__(256) __half g_Wq [DD*DD];      // transposed [N][K]
__device__ __align__(256) __half g_Wk [DD*2*DD];    // transposed [2N][K]
__device__ __align__(256) __half g_Wp [DD*DD];      // transposed [N][K]
__device__ __align__(256) __half g_q  [MR*DD];      // [B,H,S,HD]
__device__ __align__(256) __half g_k  [MR*DD];      // [B,H,Sc,HD]
__device__ __align__(256) __half g_vt [MR*DD];      // transposed [B,H,HD,Sc]
__device__ __align__(256) __half g_ao [MR*DD];      // [B,S,D]

__device__ __forceinline__ void mma16816(float* c, const uint32_t* a, uint32_t b0, uint32_t b1) {
    asm volatile(
        "mma.sync.aligned.m16n8k16.row.col.f32.f16.f16.f32 "
        "{%0,%1,%2,%3}, {%4,%5,%6,%7}, {%8,%9}, {%0,%1,%2,%3};\n"
        : "+f"(c[0]), "+f"(c[1]), "+f"(c[2]), "+f"(c[3])
        : "r"(a[0]), "r"(a[1]), "r"(a[2]), "r"(a[3]), "r"(b0), "r"(b1));
}

__device__ __forceinline__ uint32_t packh2(float lo, float hi) {
    __half2 t = __floats2half2_rn(lo, hi);
    return *reinterpret_cast<uint32_t*>(&t);
}

__device__ __forceinline__ void cpa16(uint32_t saddr, const void* g) {
    asm volatile("cp.async.cg.shared.global [%0], [%1], 16;\n" :: "r"(saddr), "l"(g));
}

// ---------------- converts ----------------
__global__ void f2h_kernel(const float* __restrict__ in, __half* __restrict__ out, int n) {
    int i = (blockIdx.x * blockDim.x + threadIdx.x) * 4;
    if (i >= n) return;
    float4 v = *(const float4*)(in + i);
    __half2 p0 = __floats2half2_rn(v.x, v.y);
    __half2 p1 = __floats2half2_rn(v.z, v.w);
    *(__half2*)(out + i)     = p0;
    *(__half2*)(out + i + 2) = p1;
}

// convert + transpose: in f32 [K][N] -> out fp16 [N][K]
__global__ __launch_bounds__(256) void f2h_T_kernel(
    const float* __restrict__ in, __half* __restrict__ out, int K, int N)
{
    __shared__ float t[32][33];
    int n0 = blockIdx.x * 32, k0 = blockIdx.y * 32;
    int r = threadIdx.x >> 3, c4 = (threadIdx.x & 7) * 4;
    float4 v = *(const float4*)(in + (size_t)(k0 + r) * N + n0 + c4);
    t[r][c4] = v.x; t[r][c4 + 1] = v.y; t[r][c4 + 2] = v.z; t[r][c4 + 3] = v.w;
    __syncthreads();
    union { __half h[4]; uint2 u; } O;
#pragma unroll
    for (int i = 0; i < 4; i++) O.h[i] = __float2half_rn(t[c4 + i][r]);
    *(uint2*)(out + (size_t)(n0 + r) * K + k0 + c4) = O.u;
}

// ---------------- GEMM with fused epilogues (HMMA fp16, 128x64 tile) ----------------
// Weights pre-transposed: Wt[N][K]; B-tile stored [n][k] in smem -> 32-bit fragment LDS.
// EPI 0: Q proj + RMSNorm*gq*0.125 -> q [B,H,S,HD]
// EPI 1: KV proj; x<16: K half + RMSNorm*gk -> k ; x>=16: V half -> TRANSPOSED [B,H,HD,Sc]
// EPI 2: out proj + bias -> f32 out
template<int EPI>
__global__ __launch_bounds__(256) void gemm_epi(
    const __half* __restrict__ A,
    const __half* __restrict__ Wt,
    const float* __restrict__ bias,
    const float* __restrict__ gvec,
    __half* __restrict__ o0,
    __half* __restrict__ o1,
    float* __restrict__ outf)
{
    __shared__ __align__(16) union SMem {
        struct {
            __half A[128][40];
            __half B[64][40];   // [n][k]
        } gm;
        float epi[128][65];
    } sm;
    __shared__ float invs[128];

    const int tid  = threadIdx.x;
    const int warp = tid >> 5, lane = tid & 31;
    const int wm = warp >> 1, wn = warp & 1;
    const int g = lane >> 2, tg = lane & 3;
    const int n0 = blockIdx.x * 64;
    const int m0 = blockIdx.y * 128;

    const int a0r = tid >> 2, a1r = (tid + 256) >> 2, ac = (tid & 3) * 8;
    const int br = tid >> 2,  bc = (tid & 3) * 8;

    float c[2][4][4];
#pragma unroll
    for (int i = 0; i < 2; i++)
#pragma unroll
        for (int j = 0; j < 4; j++)
#pragma unroll
            for (int k = 0; k < 4; k++) c[i][j][k] = 0.f;

    uint4 pA0, pA1, pB;
    {
        pA0 = *(const uint4*)(A + (size_t)(m0 + a0r) * 1024 + ac);
        pA1 = *(const uint4*)(A + (size_t)(m0 + a1r) * 1024 + ac);
        pB  = *(const uint4*)(Wt + (size_t)(n0 + br) * 1024 + bc);
    }

    for (int k0 = 0; k0 < 1024; k0 += 32) {
        *(uint4*)&sm.gm.A[a0r][ac] = pA0;
        *(uint4*)&sm.gm.A[a1r][ac] = pA1;
        *(uint4*)&sm.gm.B[br][bc]  = pB;
        __syncthreads();

        if (k0 + 32 < 1024) {
            int kn = k0 + 32;
            pA0 = *(const uint4*)(A + (size_t)(m0 + a0r) * 1024 + kn + ac);
            pA1 = *(const uint4*)(A + (size_t)(m0 + a1r) * 1024 + kn + ac);
            pB  = *(const uint4*)(Wt + (size_t)(n0 + br) * 1024 + kn + bc);
        }

#pragma unroll
        for (int kc = 0; kc < 2; kc++) {
            uint32_t a[2][4], b[4][2];
#pragma unroll
            for (int mt = 0; mt < 2; mt++) {
                int r = wm * 32 + mt * 16 + g;
                int col = kc * 16 + 2 * tg;
                a[mt][0] = *(const uint32_t*)&sm.gm.A[r][col];
                a[mt][1] = *(const uint32_t*)&sm.gm.A[r + 8][col];
                a[mt][2] = *(const uint32_t*)&sm.gm.A[r][col + 8];
                a[mt][3] = *(const uint32_t*)&sm.gm.A[r + 8][col + 8];
            }
#pragma unroll
            for (int nt = 0; nt < 4; nt++) {
                int n = wn * 32 + nt * 8 + g;
                int kk = kc * 16 + 2 * tg;
                b[nt][0] = *(const uint32_t*)&sm.gm.B[n][kk];
                b[nt][1] = *(const uint32_t*)&sm.gm.B[n][kk + 8];
            }
#pragma unroll
            for (int mt = 0; mt < 2; mt++)
#pragma unroll
                for (int nt = 0; nt < 4; nt++)
                    mma16816(c[mt][nt], a[mt], b[nt][0], b[nt][1]);
        }
        __syncthreads();
    }

#pragma unroll
    for (int mt = 0; mt < 2; mt++)
#pragma unroll
        for (int nt = 0; nt < 4; nt++) {
            int r = wm * 32 + mt * 16 + g, col = wn * 32 + nt * 8 + 2 * tg;
            sm.epi[r][col]         = c[mt][nt][0];
            sm.epi[r][col + 1]     = c[mt][nt][1];
            sm.epi[r + 8][col]     = c[mt][nt][2];
            sm.epi[r + 8][col + 1] = c[mt][nt][3];
        }
    __syncthreads();

    if (EPI == 2) {
#pragma unroll 4
        for (int idx = tid; idx < 128 * 64; idx += 256) {
            int r = idx >> 6, i = idx & 63;
            outf[(size_t)(m0 + r) * 1024 + n0 + i] = sm.epi[r][i] + bias[n0 + i];
        }
        return;
    }

    const int bidx = m0 >> 11;
    const int s0   = m0 & 2047;

    if (EPI == 1 && blockIdx.x >= 16) {
        // V half: no norm, write TRANSPOSED [bh][d][s]
        const int h = blockIdx.x & 15;
        const size_t vbase = (size_t)(bidx * HH + h) * 64;
#pragma unroll 4
        for (int idx = tid; idx < 128 * 64; idx += 256) {
            int d = idx >> 7, r = idx & 127;
            float v = sm.epi[r][d] + bias[n0 + d];
            o1[(vbase + d) * 2048 + s0 + r] = __float2half_rn(v);
        }
        return;
    }

    if (tid < 128) {
        float ss = 0.f;
#pragma unroll 8
        for (int i = 0; i < 64; i++) {
            float v = sm.epi[tid][i] + bias[n0 + i];
            ss += v * v;
        }
        invs[tid] = rsqrtf(ss * (1.0f / 64.0f) + 1e-6f);
    }
    __syncthreads();

    const int h = (EPI == 0) ? blockIdx.x : (blockIdx.x & 15);
    const float postmul = (EPI == 0) ? 0.125f : 1.0f;   // fold 1/sqrt(HD) into q
#pragma unroll 4
    for (int idx = tid; idx < 128 * 64; idx += 256) {
        int r = idx >> 6, i = idx & 63;
        float v = sm.epi[r][i] + bias[n0 + i];
        float w = v * invs[r] * gvec[i] * postmul;
        o0[((size_t)(bidx * HH + h) * 2048 + s0 + r) * 64 + i] = __float2half_rn(w);
    }
}

// ---------------- flash attention: 256 thr, 128 q-rows/CTA, cp.async 2-stage ----------------
#define ATT_STG 18432   // per stage: K tile 9216 + V tile 9216
#define ATT_SMEM (2*ATT_STG)

__global__ __launch_bounds__(256, 1) void attn_kernel(
    const __half* __restrict__ Q,
    const __half* __restrict__ K,
    const __half* __restrict__ Vt,
    __half* __restrict__ O)
{
    extern __shared__ __align__(16) char dynsmem[];
    const uint32_t sbase = (uint32_t)__cvta_generic_to_shared(dynsmem);

    const int tid = threadIdx.x, w = tid >> 5, lane = tid & 31;
    const int g = lane >> 2, tg = lane & 3;
    const int qt = blockIdx.x, h = blockIdx.y, b = blockIdx.z;
    const int bh = b * HH + h;

    const size_t koff = (size_t)bh * SS * 64;      // K [bh][t][d]
    const size_t voff = (size_t)bh * 64 * 2048;    // Vt [bh][d][s]
    const size_t qoff = koff + (size_t)qt * 128 * 64;

    const int c0row = tid >> 3,        c0off = (tid & 7) * 8;
    const int c1row = 32 + (tid >> 3), c1off = c0off;

    // Q fragments direct from gmem (once per CTA)
    uint32_t aq[4][4];
    {
        const __half* qg = Q + qoff;
        int r = w * 16 + g;
#pragma unroll
        for (int kc = 0; kc < 4; kc++) {
            int col = kc * 16 + 2 * tg;
            aq[kc][0] = *(const uint32_t*)(qg + r * 64 + col);
            aq[kc][1] = *(const uint32_t*)(qg + (r + 8) * 64 + col);
            aq[kc][2] = *(const uint32_t*)(qg + r * 64 + col + 8);
            aq[kc][3] = *(const uint32_t*)(qg + (r + 8) * 64 + col + 8);
        }
    }

    float oacc[8][4];
#pragma unroll
    for (int nt = 0; nt < 8; nt++)
#pragma unroll
        for (int i = 0; i < 4; i++) oacc[nt][i] = 0.f;
    float mrow0 = -1e30f, mrow1 = -1e30f;
    float lrow0 = 0.f, lrow1 = 0.f;

    auto issue = [&](int j, int st) {
        uint32_t sb = sbase + st * ATT_STG;
        {
            uint32_t so = c0row * 144 + c0off * 2;
            cpa16(sb + so,        K  + koff + j * 4096 + c0row * 64 + c0off);
            cpa16(sb + 9216 + so, Vt + voff + (size_t)c0row * 2048 + j * 64 + c0off);
        }
        {
            uint32_t so = c1row * 144 + c1off * 2;
            cpa16(sb + so,        K  + koff + j * 4096 + c1row * 64 + c1off);
            cpa16(sb + 9216 + so, Vt + voff + (size_t)c1row * 2048 + j * 64 + c1off);
        }
    };

    issue(0, 0);
    asm volatile("cp.async.commit_group;\n");

    for (int j = 0; j < SS / 64; j++) {
        int st = j & 1;
        if (j + 1 < SS / 64) issue(j + 1, st ^ 1);
        asm volatile("cp.async.commit_group;\n");
        asm volatile("cp.async.wait_group 1;\n");
        __syncthreads();

        __half (*ks)[72] = (__half(*)[72])(dynsmem + st * ATT_STG);
        __half (*vs)[72] = (__half(*)[72])(dynsmem + st * ATT_STG + 9216);

        // S = q @ k^T
        float sf[8][4];
#pragma unroll
        for (int nt = 0; nt < 8; nt++) {
#pragma unroll
            for (int i = 0; i < 4; i++) sf[nt][i] = 0.f;
#pragma unroll
            for (int kc = 0; kc < 4; kc++) {
                int col = kc * 16 + 2 * tg;
                int rr = nt * 8 + g;
                uint32_t b0 = *(const uint32_t*)&ks[rr][col];
                uint32_t b1 = *(const uint32_t*)&ks[rr][col + 8];
                mma16816(sf[nt], aq[kc], b0, b1);
            }
        }

        float mn0 = mrow0, mn1 = mrow1;
#pragma unroll
        for (int nt = 0; nt < 8; nt++) {
            mn0 = fmaxf(mn0, fmaxf(sf[nt][0], sf[nt][1]));
            mn1 = fmaxf(mn1, fmaxf(sf[nt][2], sf[nt][3]));
        }
        mn0 = fmaxf(mn0, __shfl_xor_sync(0xffffffffu, mn0, 1));
        mn0 = fmaxf(mn0, __shfl_xor_sync(0xffffffffu, mn0, 2));
        mn1 = fmaxf(mn1, __shfl_xor_sync(0xffffffffu, mn1, 1));
        mn1 = fmaxf(mn1, __shfl_xor_sync(0xffffffffu, mn1, 2));

        float alpha0 = __expf(mrow0 - mn0);
        float alpha1 = __expf(mrow1 - mn1);
        mrow0 = mn0; mrow1 = mn1;

        float ps0 = 0.f, ps1 = 0.f;
#pragma unroll
        for (int nt = 0; nt < 8; nt++) {
            sf[nt][0] = __expf(sf[nt][0] - mn0);
            sf[nt][1] = __expf(sf[nt][1] - mn0);
            sf[nt][2] = __expf(sf[nt][2] - mn1);
            sf[nt][3] = __expf(sf[nt][3] - mn1);
            ps0 += sf[nt][0] + sf[nt][1];
            ps1 += sf[nt][2] + sf[nt][3];
        }
        lrow0 = lrow0 * alpha0 + ps0;
        lrow1 = lrow1 * alpha1 + ps1;

        // pack P C-frags into A-frags
        uint32_t pa[4][4];
#pragma unroll
        for (int kc = 0; kc < 4; kc++) {
            pa[kc][0] = packh2(sf[2 * kc][0],     sf[2 * kc][1]);
            pa[kc][1] = packh2(sf[2 * kc][2],     sf[2 * kc][3]);
            pa[kc][2] = packh2(sf[2 * kc + 1][0], sf[2 * kc + 1][1]);
            pa[kc][3] = packh2(sf[2 * kc + 1][2], sf[2 * kc + 1][3]);
        }

#pragma unroll
        for (int nt = 0; nt < 8; nt++) {
            oacc[nt][0] *= alpha0; oacc[nt][1] *= alpha0;
            oacc[nt][2] *= alpha1; oacc[nt][3] *= alpha1;
        }

        // O += P @ V (V transposed in smem -> 32-bit fragment loads)
#pragma unroll
        for (int nt = 0; nt < 8; nt++) {
            int d = nt * 8 + g;
#pragma unroll
            for (int kc = 0; kc < 4; kc++) {
                int t0 = kc * 16 + 2 * tg;
                uint32_t b0 = *(const uint32_t*)&vs[d][t0];
                uint32_t b1 = *(const uint32_t*)&vs[d][t0 + 8];
                mma16816(oacc[nt], pa[kc], b0, b1);
            }
        }
        __syncthreads();
    }

    lrow0 += __shfl_xor_sync(0xffffffffu, lrow0, 1);
    lrow0 += __shfl_xor_sync(0xffffffffu, lrow0, 2);
    lrow1 += __shfl_xor_sync(0xffffffffu, lrow1, 1);
    lrow1 += __shfl_xor_sync(0xffffffffu, lrow1, 2);
    float i0 = 1.f / lrow0;
    float i1 = 1.f / lrow1;

    const int srow = qt * 128 + w * 16 + g;
    size_t base = ((size_t)b * SS + srow) * 1024 + h * 64;
#pragma unroll
    for (int nt = 0; nt < 8; nt++) {
        int col = nt * 8 + 2 * tg;
        *(uint32_t*)(O + base + col)            = packh2(oacc[nt][0] * i0, oacc[nt][1] * i0);
        *(uint32_t*)(O + base + 8 * 1024 + col) = packh2(oacc[nt][2] * i1, oacc[nt][3] * i1);
    }
}

extern "C" void kernel_launch(void* const* d_in, const int* in_sizes, int n_in,
                              void* d_out, int out_size)
{
    const float* x     = (const float*)d_in[0];
    const float* ctx   = (const float*)d_in[1];
    const float* Wq    = (const float*)d_in[2];
    const float* bq    = (const float*)d_in[3];
    const float* Wkv   = (const float*)d_in[4];
    const float* bkv   = (const float*)d_in[5];
    const float* Wproj = (const float*)d_in[6];
    const float* bproj = (const float*)d_in[7];
    const float* gq    = (const float*)d_in[8];
    const float* gk    = (const float*)d_in[9];

    __half *xh, *ch, *wqh, *wkh, *wph, *qh, *kh, *vth, *aoh;
    cudaGetSymbolAddress((void**)&xh,  g_x);
    cudaGetSymbolAddress((void**)&ch,  g_c);
    cudaGetSymbolAddress((void**)&wqh, g_Wq);
    cudaGetSymbolAddress((void**)&wkh, g_Wk);
    cudaGetSymbolAddress((void**)&wph, g_Wp);
    cudaGetSymbolAddress((void**)&qh,  g_q);
    cudaGetSymbolAddress((void**)&kh,  g_k);
    cudaGetSymbolAddress((void**)&vth, g_vt);
    cudaGetSymbolAddress((void**)&aoh, g_ao);

    cudaFuncSetAttribute(attn_kernel, cudaFuncAttributeMaxDynamicSharedMemorySize, ATT_SMEM);

    f2h_kernel<<<MR * DD / 1024, 256>>>(x,   xh, MR * DD);
    f2h_kernel<<<MR * DD / 1024, 256>>>(ctx, ch, MR * DD);
    f2h_T_kernel<<<dim3(32, 32), 256>>>(Wq,    wqh, 1024, 1024);
    f2h_T_kernel<<<dim3(64, 32), 256>>>(Wkv,   wkh, 1024, 2048);
    f2h_T_kernel<<<dim3(32, 32), 256>>>(Wproj, wph, 1024, 1024);

    gemm_epi<0><<<dim3(16, 64), 256>>>(xh, wqh, bq, gq, qh, nullptr, nullptr);
    gemm_epi<1><<<dim3(32, 64), 256>>>(ch, wkh, bkv, gk, kh, vth, nullptr);
    attn_kernel<<<dim3(16, 16, 4), 256, ATT_SMEM>>>(qh, kh, vth, aoh);
    gemm_epi<2><<<dim3(16, 64), 256>>>(aoh, wph, bproj, nullptr, nullptr, nullptr, (float*)d_out);
}

// round 10
// speedup vs baseline: 2.5661x; 1.1359x over previous
#include <cuda_runtime.h>
#include <cuda_fp16.h>
#include <cstdint>

#define BB 4
#define SS 2048
#define DD 1024
#define HH 16
#define HD 64
#define MR (BB*SS)

// fp16 scratch
__device__ __align__(256) __half g_x  [MR*DD];
__device__ __align__(256) __half g_c  [MR*DD];
__device__ __align__(256) __half g_Wq [DD*DD];      // transposed [N][K]
__device__ __align__(256) __half g_Wk [DD*2*DD];    // transposed [2N][K]
__device__ __align__(256) __half g_Wp [DD*DD];      // transposed [N][K]
__device__ __align__(256) __half g_q  [MR*DD];      // [B,H,S,HD]
__device__ __align__(256) __half g_k  [MR*DD];      // [B,H,Sc,HD]
__device__ __align__(256) __half g_vt [MR*DD];      // transposed [B,H,HD,Sc]
__device__ __align__(256) __half g_ao [MR*DD];      // [B,S,D]

__device__ __forceinline__ void mma16816(float* c, const uint32_t* a, uint32_t b0, uint32_t b1) {
    asm volatile(
        "mma.sync.aligned.m16n8k16.row.col.f32.f16.f16.f32 "
        "{%0,%1,%2,%3}, {%4,%5,%6,%7}, {%8,%9}, {%0,%1,%2,%3};\n"
        : "+f"(c[0]), "+f"(c[1]), "+f"(c[2]), "+f"(c[3])
        : "r"(a[0]), "r"(a[1]), "r"(a[2]), "r"(a[3]), "r"(b0), "r"(b1));
}

__device__ __forceinline__ uint32_t packh2(float lo, float hi) {
    __half2 t = __floats2half2_rn(lo, hi);
    return *reinterpret_cast<uint32_t*>(&t);
}

__device__ __forceinline__ void cpa16(uint32_t saddr, const void* g) {
    asm volatile("cp.async.cg.shared.global [%0], [%1], 16;\n" :: "r"(saddr), "l"(g));
}

// ---------------- converts ----------------
__global__ void f2h_kernel(const float* __restrict__ in, __half* __restrict__ out, int n) {
    int i = (blockIdx.x * blockDim.x + threadIdx.x) * 4;
    if (i >= n) return;
    float4 v = *(const float4*)(in + i);
    __half2 p0 = __floats2half2_rn(v.x, v.y);
    __half2 p1 = __floats2half2_rn(v.z, v.w);
    *(__half2*)(out + i)     = p0;
    *(__half2*)(out + i + 2) = p1;
}

// convert + transpose: in f32 [K][N] -> out fp16 [N][K]
__global__ __launch_bounds__(256) void f2h_T_kernel(
    const float* __restrict__ in, __half* __restrict__ out, int K, int N)
{
    __shared__ float t[32][33];
    int n0 = blockIdx.x * 32, k0 = blockIdx.y * 32;
    int r = threadIdx.x >> 3, c4 = (threadIdx.x & 7) * 4;
    float4 v = *(const float4*)(in + (size_t)(k0 + r) * N + n0 + c4);
    t[r][c4] = v.x; t[r][c4 + 1] = v.y; t[r][c4 + 2] = v.z; t[r][c4 + 3] = v.w;
    __syncthreads();
    union { __half h[4]; uint2 u; } O;
#pragma unroll
    for (int i = 0; i < 4; i++) O.h[i] = __float2half_rn(t[c4 + i][r]);
    *(uint2*)(out + (size_t)(n0 + r) * K + k0 + c4) = O.u;
}

// ---------------- GEMM, 128x128 tile, fused epilogues ----------------
// Wt[N][K] pre-transposed. 256 threads, warp grid 2(m) x 4(n); warp tile 64x32.
// Two-pass epilogue (64 cols each) so the f32 staging buffer fits static smem.
// EPI 0: Q proj + RMSNorm*gq*0.125 -> q [B,H,S,HD]
// EPI 1: x<8: K half + RMSNorm*gk -> k ; x>=8: V half -> TRANSPOSED [B,H,HD,Sc]
// EPI 2: out proj + bias -> f32 out
template<int EPI>
__global__ __launch_bounds__(256) void gemm_epi(
    const __half* __restrict__ A,
    const __half* __restrict__ Wt,
    const float* __restrict__ bias,
    const float* __restrict__ gvec,
    __half* __restrict__ o0,
    __half* __restrict__ o1,
    float* __restrict__ outf)
{
    __shared__ __align__(16) union SMem {
        struct {
            __half A[128][40];
            __half B[128][40];   // [n][k]
        } gm;
        float epi[128][65];
    } sm;
    __shared__ float invs[128];

    const int tid  = threadIdx.x;
    const int warp = tid >> 5, lane = tid & 31;
    const int wm = warp >> 2, wn = warp & 3;
    const int g = lane >> 2, tg = lane & 3;
    const int n0 = blockIdx.x * 128;
    const int m0 = blockIdx.y * 128;

    // copy indices: 512 16B chunks per tensor, 2 per thread
    const int r0 = tid >> 2, r1 = 64 + (tid >> 2), cc = (tid & 3) * 8;

    float c[4][4][4];
#pragma unroll
    for (int i = 0; i < 4; i++)
#pragma unroll
        for (int j = 0; j < 4; j++)
#pragma unroll
            for (int k = 0; k < 4; k++) c[i][j][k] = 0.f;

    uint4 pA0, pA1, pB0, pB1;
    pA0 = *(const uint4*)(A  + (size_t)(m0 + r0) * 1024 + cc);
    pA1 = *(const uint4*)(A  + (size_t)(m0 + r1) * 1024 + cc);
    pB0 = *(const uint4*)(Wt + (size_t)(n0 + r0) * 1024 + cc);
    pB1 = *(const uint4*)(Wt + (size_t)(n0 + r1) * 1024 + cc);

    for (int k0 = 0; k0 < 1024; k0 += 32) {
        *(uint4*)&sm.gm.A[r0][cc] = pA0;
        *(uint4*)&sm.gm.A[r1][cc] = pA1;
        *(uint4*)&sm.gm.B[r0][cc] = pB0;
        *(uint4*)&sm.gm.B[r1][cc] = pB1;
        __syncthreads();

        if (k0 + 32 < 1024) {
            int kn = k0 + 32;
            pA0 = *(const uint4*)(A  + (size_t)(m0 + r0) * 1024 + kn + cc);
            pA1 = *(const uint4*)(A  + (size_t)(m0 + r1) * 1024 + kn + cc);
            pB0 = *(const uint4*)(Wt + (size_t)(n0 + r0) * 1024 + kn + cc);
            pB1 = *(const uint4*)(Wt + (size_t)(n0 + r1) * 1024 + kn + cc);
        }

#pragma unroll
        for (int kc = 0; kc < 2; kc++) {
            uint32_t a[4][4], b[4][2];
#pragma unroll
            for (int mt = 0; mt < 4; mt++) {
                int r = wm * 64 + mt * 16 + g;
                int col = kc * 16 + 2 * tg;
                a[mt][0] = *(const uint32_t*)&sm.gm.A[r][col];
                a[mt][1] = *(const uint32_t*)&sm.gm.A[r + 8][col];
                a[mt][2] = *(const uint32_t*)&sm.gm.A[r][col + 8];
                a[mt][3] = *(const uint32_t*)&sm.gm.A[r + 8][col + 8];
            }
#pragma unroll
            for (int nt = 0; nt < 4; nt++) {
                int n = wn * 32 + nt * 8 + g;
                int kk = kc * 16 + 2 * tg;
                b[nt][0] = *(const uint32_t*)&sm.gm.B[n][kk];
                b[nt][1] = *(const uint32_t*)&sm.gm.B[n][kk + 8];
            }
#pragma unroll
            for (int mt = 0; mt < 4; mt++)
#pragma unroll
                for (int nt = 0; nt < 4; nt++)
                    mma16816(c[mt][nt], a[mt], b[nt][0], b[nt][1]);
        }
        __syncthreads();
    }

    const int bidx = m0 >> 11;
    const int s0   = m0 & 2047;

#pragma unroll
    for (int p = 0; p < 2; p++) {
        // warps with wn>>1 == p own cols [p*64, p*64+64)
        if ((wn >> 1) == p) {
#pragma unroll
            for (int mt = 0; mt < 4; mt++)
#pragma unroll
                for (int nt = 0; nt < 4; nt++) {
                    int r = wm * 64 + mt * 16 + g;
                    int col = (wn & 1) * 32 + nt * 8 + 2 * tg;
                    sm.epi[r][col]         = c[mt][nt][0];
                    sm.epi[r][col + 1]     = c[mt][nt][1];
                    sm.epi[r + 8][col]     = c[mt][nt][2];
                    sm.epi[r + 8][col + 1] = c[mt][nt][3];
                }
        }
        __syncthreads();

        const int nc = n0 + p * 64;

        if (EPI == 2) {
#pragma unroll 4
            for (int idx = tid; idx < 128 * 64; idx += 256) {
                int r = idx >> 6, i = idx & 63;
                outf[(size_t)(m0 + r) * 1024 + nc + i] = sm.epi[r][i] + bias[nc + i];
            }
        } else if (EPI == 1 && blockIdx.x >= 8) {
            // V half: no norm, TRANSPOSED write [bh][d][s]
            const int hv = (blockIdx.x - 8) * 2 + p;
            const size_t vbase = (size_t)(bidx * HH + hv) * 64;
#pragma unroll 4
            for (int idx = tid; idx < 128 * 64; idx += 256) {
                int d = idx >> 7, r = idx & 127;
                float v = sm.epi[r][d] + bias[nc + d];
                o1[(vbase + d) * 2048 + s0 + r] = __float2half_rn(v);
            }
        } else {
            if (tid < 128) {
                float ss = 0.f;
#pragma unroll 8
                for (int i = 0; i < 64; i++) {
                    float v = sm.epi[tid][i] + bias[nc + i];
                    ss += v * v;
                }
                invs[tid] = rsqrtf(ss * (1.0f / 64.0f) + 1e-6f);
            }
            __syncthreads();
            const int h = blockIdx.x * 2 + p;
            const float postmul = (EPI == 0) ? 0.125f : 1.0f;
#pragma unroll 4
            for (int idx = tid; idx < 128 * 64; idx += 256) {
                int r = idx >> 6, i = idx & 63;
                float v = sm.epi[r][i] + bias[nc + i];
                float w = v * invs[r] * gvec[i] * postmul;
                o0[((size_t)(bidx * HH + h) * 2048 + s0 + r) * 64 + i] = __float2half_rn(w);
            }
        }
        __syncthreads();
    }
}

// ---------------- flash attention: 256 thr, 128 q-rows/CTA, 128-wide KV tiles ----------------
#define ATT_KS 18432    // K tile: 128 rows x 72 halves
#define ATT_VS 17408    // V tile: 64 rows x 136 halves
#define ATT_STG (ATT_KS + ATT_VS)
#define ATT_SMEM (2*ATT_STG)

__global__ __launch_bounds__(256, 1) void attn_kernel(
    const __half* __restrict__ Q,
    const __half* __restrict__ K,
    const __half* __restrict__ Vt,
    __half* __restrict__ O)
{
    extern __shared__ __align__(16) char dynsmem[];
    const uint32_t sbase = (uint32_t)__cvta_generic_to_shared(dynsmem);

    const int tid = threadIdx.x, w = tid >> 5, lane = tid & 31;
    const int g = lane >> 2, tg = lane & 3;
    const int qt = blockIdx.x, h = blockIdx.y, b = blockIdx.z;
    const int bh = b * HH + h;

    const size_t koff = (size_t)bh * SS * 64;
    const size_t voff = (size_t)bh * 64 * 2048;
    const size_t qoff = koff + (size_t)qt * 128 * 64;

    // Q fragments direct from gmem (once per CTA)
    uint32_t aq[4][4];
    {
        const __half* qg = Q + qoff;
        int r = w * 16 + g;
#pragma unroll
        for (int kc = 0; kc < 4; kc++) {
            int col = kc * 16 + 2 * tg;
            aq[kc][0] = *(const uint32_t*)(qg + r * 64 + col);
            aq[kc][1] = *(const uint32_t*)(qg + (r + 8) * 64 + col);
            aq[kc][2] = *(const uint32_t*)(qg + r * 64 + col + 8);
            aq[kc][3] = *(const uint32_t*)(qg + (r + 8) * 64 + col + 8);
        }
    }

    float oacc[8][4];
#pragma unroll
    for (int nt = 0; nt < 8; nt++)
#pragma unroll
        for (int i = 0; i < 4; i++) oacc[nt][i] = 0.f;
    float mrow0 = -1e30f, mrow1 = -1e30f;
    float lrow0 = 0.f, lrow1 = 0.f;

    // tile j covers kv rows [j*128, j*128+128)
    auto issue = [&](int j, int st) {
        uint32_t sb = sbase + st * ATT_STG;
        // K tile: 128 rows x 64 d, 4 chunks/thread
#pragma unroll
        for (int t = 0; t < 4; t++) {
            int row = (tid >> 3) + t * 32;
            int col = (tid & 7) * 8;
            cpa16(sb + row * 144 + col * 2, K + koff + j * 8192 + row * 64 + col);
        }
        // V tile (transposed): 64 d-rows x 128 t, 4 chunks/thread
#pragma unroll
        for (int t = 0; t < 4; t++) {
            int d = (tid >> 4) + t * 16;
            int cl = (tid & 15) * 8;
            cpa16(sb + ATT_KS + d * 272 + cl * 2, Vt + voff + (size_t)d * 2048 + j * 128 + cl);
        }
    };

    issue(0, 0);
    asm volatile("cp.async.commit_group;\n");

    for (int j = 0; j < SS / 128; j++) {
        int st = j & 1;
        if (j + 1 < SS / 128) issue(j + 1, st ^ 1);
        asm volatile("cp.async.commit_group;\n");
        asm volatile("cp.async.wait_group 1;\n");
        __syncthreads();

        __half (*ks)[72]  = (__half(*)[72])(dynsmem + st * ATT_STG);
        __half (*vs)[136] = (__half(*)[136])(dynsmem + st * ATT_STG + ATT_KS);

        // S = q @ k^T : 16 n-tiles of 8 kv
        float sf[16][4];
#pragma unroll
        for (int nt = 0; nt < 16; nt++) {
#pragma unroll
            for (int i = 0; i < 4; i++) sf[nt][i] = 0.f;
#pragma unroll
            for (int kc = 0; kc < 4; kc++) {
                int col = kc * 16 + 2 * tg;
                int rr = nt * 8 + g;
                uint32_t b0 = *(const uint32_t*)&ks[rr][col];
                uint32_t b1 = *(const uint32_t*)&ks[rr][col + 8];
                mma16816(sf[nt], aq[kc], b0, b1);
            }
        }

        float mn0 = mrow0, mn1 = mrow1;
#pragma unroll
        for (int nt = 0; nt < 16; nt++) {
            mn0 = fmaxf(mn0, fmaxf(sf[nt][0], sf[nt][1]));
            mn1 = fmaxf(mn1, fmaxf(sf[nt][2], sf[nt][3]));
        }
        mn0 = fmaxf(mn0, __shfl_xor_sync(0xffffffffu, mn0, 1));
        mn0 = fmaxf(mn0, __shfl_xor_sync(0xffffffffu, mn0, 2));
        mn1 = fmaxf(mn1, __shfl_xor_sync(0xffffffffu, mn1, 1));
        mn1 = fmaxf(mn1, __shfl_xor_sync(0xffffffffu, mn1, 2));

        float alpha0 = __expf(mrow0 - mn0);
        float alpha1 = __expf(mrow1 - mn1);
        mrow0 = mn0; mrow1 = mn1;

        float ps0 = 0.f, ps1 = 0.f;
#pragma unroll
        for (int nt = 0; nt < 16; nt++) {
            sf[nt][0] = __expf(sf[nt][0] - mn0);
            sf[nt][1] = __expf(sf[nt][1] - mn0);
            sf[nt][2] = __expf(sf[nt][2] - mn1);
            sf[nt][3] = __expf(sf[nt][3] - mn1);
            ps0 += sf[nt][0] + sf[nt][1];
            ps1 += sf[nt][2] + sf[nt][3];
        }
        lrow0 = lrow0 * alpha0 + ps0;
        lrow1 = lrow1 * alpha1 + ps1;

        // pack P C-frags into A-frags (k dim = 128 kv -> 8 kc)
        uint32_t pa[8][4];
#pragma unroll
        for (int kc = 0; kc < 8; kc++) {
            pa[kc][0] = packh2(sf[2 * kc][0],     sf[2 * kc][1]);
            pa[kc][1] = packh2(sf[2 * kc][2],     sf[2 * kc][3]);
            pa[kc][2] = packh2(sf[2 * kc + 1][0], sf[2 * kc + 1][1]);
            pa[kc][3] = packh2(sf[2 * kc + 1][2], sf[2 * kc + 1][3]);
        }

#pragma unroll
        for (int nt = 0; nt < 8; nt++) {
            oacc[nt][0] *= alpha0; oacc[nt][1] *= alpha0;
            oacc[nt][2] *= alpha1; oacc[nt][3] *= alpha1;
        }

        // O += P @ V
#pragma unroll
        for (int nt = 0; nt < 8; nt++) {
            int d = nt * 8 + g;
#pragma unroll
            for (int kc = 0; kc < 8; kc++) {
                int t0 = kc * 16 + 2 * tg;
                uint32_t b0 = *(const uint32_t*)&vs[d][t0];
                uint32_t b1 = *(const uint32_t*)&vs[d][t0 + 8];
                mma16816(oacc[nt], pa[kc], b0, b1);
            }
        }
        __syncthreads();
    }

    lrow0 += __shfl_xor_sync(0xffffffffu, lrow0, 1);
    lrow0 += __shfl_xor_sync(0xffffffffu, lrow0, 2);
    lrow1 += __shfl_xor_sync(0xffffffffu, lrow1, 1);
    lrow1 += __shfl_xor_sync(0xffffffffu, lrow1, 2);
    float i0 = 1.f / lrow0;
    float i1 = 1.f / lrow1;

    const int srow = qt * 128 + w * 16 + g;
    size_t base = ((size_t)b * SS + srow) * 1024 + h * 64;
#pragma unroll
    for (int nt = 0; nt < 8; nt++) {
        int col = nt * 8 + 2 * tg;
        *(uint32_t*)(O + base + col)            = packh2(oacc[nt][0] * i0, oacc[nt][1] * i0);
        *(uint32_t*)(O + base + 8 * 1024 + col) = packh2(oacc[nt][2] * i1, oacc[nt][3] * i1);
    }
}

extern "C" void kernel_launch(void* const* d_in, const int* in_sizes, int n_in,
                              void* d_out, int out_size)
{
    const float* x     = (const float*)d_in[0];
    const float* ctx   = (const float*)d_in[1];
    const float* Wq    = (const float*)d_in[2];
    const float* bq    = (const float*)d_in[3];
    const float* Wkv   = (const float*)d_in[4];
    const float* bkv   = (const float*)d_in[5];
    const float* Wproj = (const float*)d_in[6];
    const float* bproj = (const float*)d_in[7];
    const float* gq    = (const float*)d_in[8];
    const float* gk    = (const float*)d_in[9];

    __half *xh, *ch, *wqh, *wkh, *wph, *qh, *kh, *vth, *aoh;
    cudaGetSymbolAddress((void**)&xh,  g_x);
    cudaGetSymbolAddress((void**)&ch,  g_c);
    cudaGetSymbolAddress((void**)&wqh, g_Wq);
    cudaGetSymbolAddress((void**)&wkh, g_Wk);
    cudaGetSymbolAddress((void**)&wph, g_Wp);
    cudaGetSymbolAddress((void**)&qh,  g_q);
    cudaGetSymbolAddress((void**)&kh,  g_k);
    cudaGetSymbolAddress((void**)&vth, g_vt);
    cudaGetSymbolAddress((void**)&aoh, g_ao);

    cudaFuncSetAttribute(attn_kernel, cudaFuncAttributeMaxDynamicSharedMemorySize, ATT_SMEM);

    f2h_kernel<<<MR * DD / 1024, 256>>>(x,   xh, MR * DD);
    f2h_kernel<<<MR * DD / 1024, 256>>>(ctx, ch, MR * DD);
    f2h_T_kernel<<<dim3(32, 32), 256>>>(Wq,    wqh, 1024, 1024);
    f2h_T_kernel<<<dim3(64, 32), 256>>>(Wkv,   wkh, 1024, 2048);
    f2h_T_kernel<<<dim3(32, 32), 256>>>(Wproj, wph, 1024, 1024);

    gemm_epi<0><<<dim3(8, 64), 256>>>(xh, wqh, bq, gq, qh, nullptr, nullptr);
    gemm_epi<1><<<dim3(16, 64), 256>>>(ch, wkh, bkv, gk, kh, vth, nullptr);
    attn_kernel<<<dim3(16, 16, 4), 256, ATT_SMEM>>>(qh, kh, vth, aoh);
    gemm_epi<2><<<dim3(8, 64), 256>>>(aoh, wph, bproj, nullptr, nullptr, nullptr, (float*)d_out);
}

// round 13
// speedup vs baseline: 3.0290x; 1.1804x over previous
#include <cuda_runtime.h>
#include <cuda_fp16.h>
#include <cstdint>

#define BB 4
#define SS 2048
#define DD 1024
#define HH 16
#define HD 64
#define MR (BB*SS)

// fp16 scratch
__device__ __align__(256) __half g_x  [MR*DD];
__device__ __align__(256) __half g_c  [MR*DD];
__device__ __align__(256) __half g_Wq [DD*DD];      // transposed [N][K]
__device__ __align__(256) __half g_Wk [DD*2*DD];    // transposed [2N][K]
__device__ __align__(256) __half g_Wp [DD*DD];      // transposed [N][K]
__device__ __align__(256) __half g_q  [MR*DD];      // [B,H,S,HD]
__device__ __align__(256) __half g_k  [MR*DD];      // [B,H,Sc,HD]
__device__ __align__(256) __half g_vt [MR*DD];      // transposed [B,H,HD,Sc]
__device__ __align__(256) __half g_ao [MR*DD];      // [B,S,D]

__device__ __forceinline__ void mma16816(float* c, const uint32_t* a, uint32_t b0, uint32_t b1) {
    asm volatile(
        "mma.sync.aligned.m16n8k16.row.col.f32.f16.f16.f32 "
        "{%0,%1,%2,%3}, {%4,%5,%6,%7}, {%8,%9}, {%0,%1,%2,%3};\n"
        : "+f"(c[0]), "+f"(c[1]), "+f"(c[2]), "+f"(c[3])
        : "r"(a[0]), "r"(a[1]), "r"(a[2]), "r"(a[3]), "r"(b0), "r"(b1));
}

__device__ __forceinline__ uint32_t packh2(float lo, float hi) {
    __half2 t = __floats2half2_rn(lo, hi);
    return *reinterpret_cast<uint32_t*>(&t);
}

__device__ __forceinline__ void cpa16(uint32_t saddr, const void* g) {
    asm volatile("cp.async.cg.shared.global [%0], [%1], 16;\n" :: "r"(saddr), "l"(g));
}

// ---------------- converts ----------------
__global__ void f2h_kernel(const float* __restrict__ in, __half* __restrict__ out, int n) {
    int i = (blockIdx.x * blockDim.x + threadIdx.x) * 4;
    if (i >= n) return;
    float4 v = *(const float4*)(in + i);
    __half2 p0 = __floats2half2_rn(v.x, v.y);
    __half2 p1 = __floats2half2_rn(v.z, v.w);
    *(__half2*)(out + i)     = p0;
    *(__half2*)(out + i + 2) = p1;
}

// convert + transpose: in f32 [K][N] -> out fp16 [N][K]
__global__ __launch_bounds__(256) void f2h_T_kernel(
    const float* __restrict__ in, __half* __restrict__ out, int K, int N)
{
    __shared__ float t[32][33];
    int n0 = blockIdx.x * 32, k0 = blockIdx.y * 32;
    int r = threadIdx.x >> 3, c4 = (threadIdx.x & 7) * 4;
    float4 v = *(const float4*)(in + (size_t)(k0 + r) * N + n0 + c4);
    t[r][c4] = v.x; t[r][c4 + 1] = v.y; t[r][c4 + 2] = v.z; t[r][c4 + 3] = v.w;
    __syncthreads();
    union { __half h[4]; uint2 u; } O;
#pragma unroll
    for (int i = 0; i < 4; i++) O.h[i] = __float2half_rn(t[c4 + i][r]);
    *(uint2*)(out + (size_t)(n0 + r) * K + k0 + c4) = O.u;
}

// ---------------- GEMM, 128x128 tile, k-slab 64, fused epilogues ----------------
// Wt[N][K] pre-transposed. 256 threads, warp grid 2(m) x 4(n); warp tile 64x32.
// EPI 0: Q proj + RMSNorm*gq*0.125 -> q [B,H,S,HD]
// EPI 1: x<8: K half + RMSNorm*gk -> k ; x>=8: V half -> TRANSPOSED [B,H,HD,Sc]
// EPI 2: out proj + bias -> f32 out
template<int EPI>
__global__ __launch_bounds__(256) void gemm_epi(
    const __half* __restrict__ A,
    const __half* __restrict__ Wt,
    const float* __restrict__ bias,
    const float* __restrict__ gvec,
    __half* __restrict__ o0,
    __half* __restrict__ o1,
    float* __restrict__ outf)
{
    __shared__ __align__(16) union SMem {
        struct {
            __half A[128][72];
            __half B[128][72];   // [n][k]
        } gm;
        float epi[128][65];
    } sm;
    __shared__ float invs[128];

    const int tid  = threadIdx.x;
    const int warp = tid >> 5, lane = tid & 31;
    const int wm = warp >> 2, wn = warp & 3;
    const int g = lane >> 2, tg = lane & 3;
    const int n0 = blockIdx.x * 128;
    const int m0 = blockIdx.y * 128;

    float c[4][4][4];
#pragma unroll
    for (int i = 0; i < 4; i++)
#pragma unroll
        for (int j = 0; j < 4; j++)
#pragma unroll
            for (int k = 0; k < 4; k++) c[i][j][k] = 0.f;

    // 4 16B-chunks per tensor per thread (1024 chunks per tensor per 64-k slab)
    uint4 pA[4], pB[4];
#pragma unroll
    for (int t = 0; t < 4; t++) {
        int cc = tid + t * 256;
        int row = cc >> 3, col = (cc & 7) * 8;
        pA[t] = *(const uint4*)(A  + (size_t)(m0 + row) * 1024 + col);
        pB[t] = *(const uint4*)(Wt + (size_t)(n0 + row) * 1024 + col);
    }

    for (int k0 = 0; k0 < 1024; k0 += 64) {
#pragma unroll
        for (int t = 0; t < 4; t++) {
            int cc = tid + t * 256;
            int row = cc >> 3, col = (cc & 7) * 8;
            *(uint4*)&sm.gm.A[row][col] = pA[t];
            *(uint4*)&sm.gm.B[row][col] = pB[t];
        }
        __syncthreads();

        if (k0 + 64 < 1024) {
            int kn = k0 + 64;
#pragma unroll
            for (int t = 0; t < 4; t++) {
                int cc = tid + t * 256;
                int row = cc >> 3, col = (cc & 7) * 8;
                pA[t] = *(const uint4*)(A  + (size_t)(m0 + row) * 1024 + kn + col);
                pB[t] = *(const uint4*)(Wt + (size_t)(n0 + row) * 1024 + kn + col);
            }
        }

#pragma unroll
        for (int kc = 0; kc < 4; kc++) {
            uint32_t a[4][4], b[4][2];
#pragma unroll
            for (int mt = 0; mt < 4; mt++) {
                int r = wm * 64 + mt * 16 + g;
                int col = kc * 16 + 2 * tg;
                a[mt][0] = *(const uint32_t*)&sm.gm.A[r][col];
                a[mt][1] = *(const uint32_t*)&sm.gm.A[r + 8][col];
                a[mt][2] = *(const uint32_t*)&sm.gm.A[r][col + 8];
                a[mt][3] = *(const uint32_t*)&sm.gm.A[r + 8][col + 8];
            }
#pragma unroll
            for (int nt = 0; nt < 4; nt++) {
                int n = wn * 32 + nt * 8 + g;
                int kk = kc * 16 + 2 * tg;
                b[nt][0] = *(const uint32_t*)&sm.gm.B[n][kk];
                b[nt][1] = *(const uint32_t*)&sm.gm.B[n][kk + 8];
            }
#pragma unroll
            for (int mt = 0; mt < 4; mt++)
#pragma unroll
                for (int nt = 0; nt < 4; nt++)
                    mma16816(c[mt][nt], a[mt], b[nt][0], b[nt][1]);
        }
        __syncthreads();
    }

    const int bidx = m0 >> 11;
    const int s0   = m0 & 2047;

#pragma unroll
    for (int p = 0; p < 2; p++) {
        // warps with wn>>1 == p own cols [p*64, p*64+64)
        if ((wn >> 1) == p) {
#pragma unroll
            for (int mt = 0; mt < 4; mt++)
#pragma unroll
                for (int nt = 0; nt < 4; nt++) {
                    int r = wm * 64 + mt * 16 + g;
                    int col = (wn & 1) * 32 + nt * 8 + 2 * tg;
                    sm.epi[r][col]         = c[mt][nt][0];
                    sm.epi[r][col + 1]     = c[mt][nt][1];
                    sm.epi[r + 8][col]     = c[mt][nt][2];
                    sm.epi[r + 8][col + 1] = c[mt][nt][3];
                }
        }
        __syncthreads();

        const int nc = n0 + p * 64;

        if (EPI == 2) {
#pragma unroll 4
            for (int idx = tid; idx < 128 * 64; idx += 256) {
                int r = idx >> 6, i = idx & 63;
                outf[(size_t)(m0 + r) * 1024 + nc + i] = sm.epi[r][i] + bias[nc + i];
            }
        } else if (EPI == 1 && blockIdx.x >= 8) {
            // V half: no norm, TRANSPOSED write [bh][d][s]
            const int hv = (blockIdx.x - 8) * 2 + p;
            const size_t vbase = (size_t)(bidx * HH + hv) * 64;
#pragma unroll 4
            for (int idx = tid; idx < 128 * 64; idx += 256) {
                int d = idx >> 7, r = idx & 127;
                float v = sm.epi[r][d] + bias[nc + d];
                o1[(vbase + d) * 2048 + s0 + r] = __float2half_rn(v);
            }
        } else {
            if (tid < 128) {
                float ss = 0.f;
#pragma unroll 8
                for (int i = 0; i < 64; i++) {
                    float v = sm.epi[tid][i] + bias[nc + i];
                    ss += v * v;
                }
                invs[tid] = rsqrtf(ss * (1.0f / 64.0f) + 1e-6f);
            }
            __syncthreads();
            const int h = blockIdx.x * 2 + p;
            const float postmul = (EPI == 0) ? 0.125f : 1.0f;
#pragma unroll 4
            for (int idx = tid; idx < 128 * 64; idx += 256) {
                int r = idx >> 6, i = idx & 63;
                float v = sm.epi[r][i] + bias[nc + i];
                float w = v * invs[r] * gvec[i] * postmul;
                o0[((size_t)(bidx * HH + h) * 2048 + s0 + r) * 64 + i] = __float2half_rn(w);
            }
        }
        __syncthreads();
    }
}

// ---------------- flash attention: 256 thr, 128 q-rows/CTA, 128-wide KV tiles ----------------
// Streaming softmax WITHOUT online max: |score| <= |q||k| = 1*8 = 8 by Cauchy-Schwarz
// (q is RMS-normalized and scaled by 0.125 -> ||q||=1; k is RMS-normalized -> ||k||=8),
// so exp(score) <= e^8 ~ 2981: safe in f32 accumulation AND within fp16 range for P.
#define ATT_KS 18432    // K tile: 128 rows x 72 halves
#define ATT_VS 17408    // V tile: 64 rows x 136 halves
#define ATT_STG (ATT_KS + ATT_VS)
#define ATT_SMEM (2*ATT_STG)

__global__ __launch_bounds__(256, 1) void attn_kernel(
    const __half* __restrict__ Q,
    const __half* __restrict__ K,
    const __half* __restrict__ Vt,
    __half* __restrict__ O)
{
    extern __shared__ __align__(16) char dynsmem[];
    const uint32_t sbase = (uint32_t)__cvta_generic_to_shared(dynsmem);

    const int tid = threadIdx.x, w = tid >> 5, lane = tid & 31;
    const int g = lane >> 2, tg = lane & 3;
    const int qt = blockIdx.x, h = blockIdx.y, b = blockIdx.z;
    const int bh = b * HH + h;

    const size_t koff = (size_t)bh * SS * 64;
    const size_t voff = (size_t)bh * 64 * 2048;
    const size_t qoff = koff + (size_t)qt * 128 * 64;

    // Q fragments direct from gmem (once per CTA)
    uint32_t aq[4][4];
    {
        const __half* qg = Q + qoff;
        int r = w * 16 + g;
#pragma unroll
        for (int kc = 0; kc < 4; kc++) {
            int col = kc * 16 + 2 * tg;
            aq[kc][0] = *(const uint32_t*)(qg + r * 64 + col);
            aq[kc][1] = *(const uint32_t*)(qg + (r + 8) * 64 + col);
            aq[kc][2] = *(const uint32_t*)(qg + r * 64 + col + 8);
            aq[kc][3] = *(const uint32_t*)(qg + (r + 8) * 64 + col + 8);
        }
    }

    float oacc[8][4];
#pragma unroll
    for (int nt = 0; nt < 8; nt++)
#pragma unroll
        for (int i = 0; i < 4; i++) oacc[nt][i] = 0.f;
    float lrow0 = 0.f, lrow1 = 0.f;

    // tile j covers kv rows [j*128, j*128+128)
    auto issue = [&](int j, int st) {
        uint32_t sb = sbase + st * ATT_STG;
        // K tile: 128 rows x 64 d, 4 chunks/thread
#pragma unroll
        for (int t = 0; t < 4; t++) {
            int row = (tid >> 3) + t * 32;
            int col = (tid & 7) * 8;
            cpa16(sb + row * 144 + col * 2, K + koff + j * 8192 + row * 64 + col);
        }
        // V tile (transposed): 64 d-rows x 128 t, 4 chunks/thread
#pragma unroll
        for (int t = 0; t < 4; t++) {
            int d = (tid >> 4) + t * 16;
            int cl = (tid & 15) * 8;
            cpa16(sb + ATT_KS + d * 272 + cl * 2, Vt + voff + (size_t)d * 2048 + j * 128 + cl);
        }
    };

    issue(0, 0);
    asm volatile("cp.async.commit_group;\n");

    for (int j = 0; j < SS / 128; j++) {
        int st = j & 1;
        if (j + 1 < SS / 128) issue(j + 1, st ^ 1);
        asm volatile("cp.async.commit_group;\n");
        asm volatile("cp.async.wait_group 1;\n");
        __syncthreads();

        __half (*ks)[72]  = (__half(*)[72])(dynsmem + st * ATT_STG);
        __half (*vs)[136] = (__half(*)[136])(dynsmem + st * ATT_STG + ATT_KS);

        // S = q @ k^T : 16 n-tiles of 8 kv
        float sf[16][4];
#pragma unroll
        for (int nt = 0; nt < 16; nt++) {
#pragma unroll
            for (int i = 0; i < 4; i++) sf[nt][i] = 0.f;
#pragma unroll
            for (int kc = 0; kc < 4; kc++) {
                int col = kc * 16 + 2 * tg;
                int rr = nt * 8 + g;
                uint32_t b0 = *(const uint32_t*)&ks[rr][col];
                uint32_t b1 = *(const uint32_t*)&ks[rr][col + 8];
                mma16816(sf[nt], aq[kc], b0, b1);
            }
        }

        // streaming exp (no max subtraction; scores bounded by +-8)
        float ps0 = 0.f, ps1 = 0.f;
#pragma unroll
        for (int nt = 0; nt < 16; nt++) {
            sf[nt][0] = __expf(sf[nt][0]);
            sf[nt][1] = __expf(sf[nt][1]);
            sf[nt][2] = __expf(sf[nt][2]);
            sf[nt][3] = __expf(sf[nt][3]);
            ps0 += sf[nt][0] + sf[nt][1];
            ps1 += sf[nt][2] + sf[nt][3];
        }
        lrow0 += ps0;
        lrow1 += ps1;

        // pack P C-frags into A-frags (k dim = 128 kv -> 8 kc)
        uint32_t pa[8][4];
#pragma unroll
        for (int kc = 0; kc < 8; kc++) {
            pa[kc][0] = packh2(sf[2 * kc][0],     sf[2 * kc][1]);
            pa[kc][1] = packh2(sf[2 * kc][2],     sf[2 * kc][3]);
            pa[kc][2] = packh2(sf[2 * kc + 1][0], sf[2 * kc + 1][1]);
            pa[kc][3] = packh2(sf[2 * kc + 1][2], sf[2 * kc + 1][3]);
        }

        // O += P @ V (no rescale needed)
#pragma unroll
        for (int nt = 0; nt < 8; nt++) {
            int d = nt * 8 + g;
#pragma unroll
            for (int kc = 0; kc < 8; kc++) {
                int t0 = kc * 16 + 2 * tg;
                uint32_t b0 = *(const uint32_t*)&vs[d][t0];
                uint32_t b1 = *(const uint32_t*)&vs[d][t0 + 8];
                mma16816(oacc[nt], pa[kc], b0, b1);
            }
        }
        __syncthreads();
    }

    lrow0 += __shfl_xor_sync(0xffffffffu, lrow0, 1);
    lrow0 += __shfl_xor_sync(0xffffffffu, lrow0, 2);
    lrow1 += __shfl_xor_sync(0xffffffffu, lrow1, 1);
    lrow1 += __shfl_xor_sync(0xffffffffu, lrow1, 2);
    float i0 = 1.f / lrow0;
    float i1 = 1.f / lrow1;

    const int srow = qt * 128 + w * 16 + g;
    size_t base = ((size_t)b * SS + srow) * 1024 + h * 64;
#pragma unroll
    for (int nt = 0; nt < 8; nt++) {
        int col = nt * 8 + 2 * tg;
        *(uint32_t*)(O + base + col)            = packh2(oacc[nt][0] * i0, oacc[nt][1] * i0);
        *(uint32_t*)(O + base + 8 * 1024 + col) = packh2(oacc[nt][2] * i1, oacc[nt][3] * i1);
    }
}

extern "C" void kernel_launch(void* const* d_in, const int* in_sizes, int n_in,
                              void* d_out, int out_size)
{
    const float* x     = (const float*)d_in[0];
    const float* ctx   = (const float*)d_in[1];
    const float* Wq    = (const float*)d_in[2];
    const float* bq    = (const float*)d_in[3];
    const float* Wkv   = (const float*)d_in[4];
    const float* bkv   = (const float*)d_in[5];
    const float* Wproj = (const float*)d_in[6];
    const float* bproj = (const float*)d_in[7];
    const float* gq    = (const float*)d_in[8];
    const float* gk    = (const float*)d_in[9];

    __half *xh, *ch, *wqh, *wkh, *wph, *qh, *kh, *vth, *aoh;
    cudaGetSymbolAddress((void**)&xh,  g_x);
    cudaGetSymbolAddress((void**)&ch,  g_c);
    cudaGetSymbolAddress((void**)&wqh, g_Wq);
    cudaGetSymbolAddress((void**)&wkh, g_Wk);
    cudaGetSymbolAddress((void**)&wph, g_Wp);
    cudaGetSymbolAddress((void**)&qh,  g_q);
    cudaGetSymbolAddress((void**)&kh,  g_k);
    cudaGetSymbolAddress((void**)&vth, g_vt);
    cudaGetSymbolAddress((void**)&aoh, g_ao);

    cudaFuncSetAttribute(attn_kernel, cudaFuncAttributeMaxDynamicSharedMemorySize, ATT_SMEM);

    f2h_kernel<<<MR * DD / 1024, 256>>>(x,   xh, MR * DD);
    f2h_kernel<<<MR * DD / 1024, 256>>>(ctx, ch, MR * DD);
    f2h_T_kernel<<<dim3(32, 32), 256>>>(Wq,    wqh, 1024, 1024);
    f2h_T_kernel<<<dim3(64, 32), 256>>>(Wkv,   wkh, 1024, 2048);
    f2h_T_kernel<<<dim3(32, 32), 256>>>(Wproj, wph, 1024, 1024);

    gemm_epi<0><<<dim3(8, 64), 256>>>(xh, wqh, bq, gq, qh, nullptr, nullptr);
    gemm_epi<1><<<dim3(16, 64), 256>>>(ch, wkh, bkv, gk, kh, vth, nullptr);
    attn_kernel<<<dim3(16, 16, 4), 256, ATT_SMEM>>>(qh, kh, vth, aoh);
    gemm_epi<2><<<dim3(8, 64), 256>>>(aoh, wph, bproj, nullptr, nullptr, nullptr, (float*)d_out);
}

// round 15
// speedup vs baseline: 3.0498x; 1.0068x over previous
#include <cuda_runtime.h>
#include <cuda_fp16.h>
#include <cstdint>

#define BB 4
#define SS 2048
#define DD 1024
#define HH 16
#define HD 64
#define MR (BB*SS)

// fp16 scratch
__device__ __align__(256) __half g_x  [MR*DD];
__device__ __align__(256) __half g_c  [MR*DD];
__device__ __align__(256) __half g_Wq [DD*DD];      // transposed [N][K]
__device__ __align__(256) __half g_Wk [DD*2*DD];    // transposed [2N][K]
__device__ __align__(256) __half g_Wp [DD*DD];      // transposed [N][K]
__device__ __align__(256) __half g_q  [MR*DD];      // [B,H,S,HD] (scaled by 0.125*log2e)
__device__ __align__(256) __half g_k  [MR*DD];      // [B,H,Sc,HD]
__device__ __align__(256) __half g_vt [MR*DD];      // transposed [B,H,HD,Sc]
__device__ __align__(256) __half g_ao [MR*DD];      // [B,S,D]

__device__ __forceinline__ void mma16816(float* c, const uint32_t* a, uint32_t b0, uint32_t b1) {
    asm volatile(
        "mma.sync.aligned.m16n8k16.row.col.f32.f16.f16.f32 "
        "{%0,%1,%2,%3}, {%4,%5,%6,%7}, {%8,%9}, {%0,%1,%2,%3};\n"
        : "+f"(c[0]), "+f"(c[1]), "+f"(c[2]), "+f"(c[3])
        : "r"(a[0]), "r"(a[1]), "r"(a[2]), "r"(a[3]), "r"(b0), "r"(b1));
}

__device__ __forceinline__ uint32_t packh2(float lo, float hi) {
    __half2 t = __floats2half2_rn(lo, hi);
    return *reinterpret_cast<uint32_t*>(&t);
}

__device__ __forceinline__ float ex2f(float x) {
    float y;
    asm("ex2.approx.f32 %0, %1;" : "=f"(y) : "f"(x));
    return y;
}

__device__ __forceinline__ void cpa16(uint32_t saddr, const void* g) {
    asm volatile("cp.async.cg.shared.global [%0], [%1], 16;\n" :: "r"(saddr), "l"(g));
}

// ---------------- converts ----------------
__global__ void f2h_kernel(const float* __restrict__ in, __half* __restrict__ out, int n) {
    int i = (blockIdx.x * blockDim.x + threadIdx.x) * 4;
    if (i >= n) return;
    float4 v = *(const float4*)(in + i);
    __half2 p0 = __floats2half2_rn(v.x, v.y);
    __half2 p1 = __floats2half2_rn(v.z, v.w);
    *(__half2*)(out + i)     = p0;
    *(__half2*)(out + i + 2) = p1;
}

// convert + transpose: in f32 [K][N] -> out fp16 [N][K]
__global__ __launch_bounds__(256) void f2h_T_kernel(
    const float* __restrict__ in, __half* __restrict__ out, int K, int N)
{
    __shared__ float t[32][33];
    int n0 = blockIdx.x * 32, k0 = blockIdx.y * 32;
    int r = threadIdx.x >> 3, c4 = (threadIdx.x & 7) * 4;
    float4 v = *(const float4*)(in + (size_t)(k0 + r) * N + n0 + c4);
    t[r][c4] = v.x; t[r][c4 + 1] = v.y; t[r][c4 + 2] = v.z; t[r][c4 + 3] = v.w;
    __syncthreads();
    union { __half h[4]; uint2 u; } O;
#pragma unroll
    for (int i = 0; i < 4; i++) O.h[i] = __float2half_rn(t[c4 + i][r]);
    *(uint2*)(out + (size_t)(n0 + r) * K + k0 + c4) = O.u;
}

// ---------------- GEMM, 128x128 tile, k-slab 64, fused epilogues ----------------
// Wt[N][K] pre-transposed. 256 threads, warp grid 2(m) x 4(n); warp tile 64x32.
// EPI 0: Q proj + RMSNorm*gq*(0.125*log2e) -> q [B,H,S,HD]
// EPI 1: x<8: K half + RMSNorm*gk -> k ; x>=8: V half -> TRANSPOSED [B,H,HD,Sc]
// EPI 2: out proj + bias -> f32 out
template<int EPI>
__global__ __launch_bounds__(256) void gemm_epi(
    const __half* __restrict__ A,
    const __half* __restrict__ Wt,
    const float* __restrict__ bias,
    const float* __restrict__ gvec,
    __half* __restrict__ o0,
    __half* __restrict__ o1,
    float* __restrict__ outf)
{
    __shared__ __align__(16) union SMem {
        struct {
            __half A[128][72];
            __half B[128][72];   // [n][k]
        } gm;
        float epi[128][65];
    } sm;
    __shared__ float invs[128];

    const int tid  = threadIdx.x;
    const int warp = tid >> 5, lane = tid & 31;
    const int wm = warp >> 2, wn = warp & 3;
    const int g = lane >> 2, tg = lane & 3;
    const int n0 = blockIdx.x * 128;
    const int m0 = blockIdx.y * 128;

    float c[4][4][4];
#pragma unroll
    for (int i = 0; i < 4; i++)
#pragma unroll
        for (int j = 0; j < 4; j++)
#pragma unroll
            for (int k = 0; k < 4; k++) c[i][j][k] = 0.f;

    // 4 16B-chunks per tensor per thread (1024 chunks per tensor per 64-k slab)
    uint4 pA[4], pB[4];
#pragma unroll
    for (int t = 0; t < 4; t++) {
        int cc = tid + t * 256;
        int row = cc >> 3, col = (cc & 7) * 8;
        pA[t] = *(const uint4*)(A  + (size_t)(m0 + row) * 1024 + col);
        pB[t] = *(const uint4*)(Wt + (size_t)(n0 + row) * 1024 + col);
    }

    for (int k0 = 0; k0 < 1024; k0 += 64) {
#pragma unroll
        for (int t = 0; t < 4; t++) {
            int cc = tid + t * 256;
            int row = cc >> 3, col = (cc & 7) * 8;
            *(uint4*)&sm.gm.A[row][col] = pA[t];
            *(uint4*)&sm.gm.B[row][col] = pB[t];
        }
        __syncthreads();

        if (k0 + 64 < 1024) {
            int kn = k0 + 64;
#pragma unroll
            for (int t = 0; t < 4; t++) {
                int cc = tid + t * 256;
                int row = cc >> 3, col = (cc & 7) * 8;
                pA[t] = *(const uint4*)(A  + (size_t)(m0 + row) * 1024 + kn + col);
                pB[t] = *(const uint4*)(Wt + (size_t)(n0 + row) * 1024 + kn + col);
            }
        }

#pragma unroll
        for (int kc = 0; kc < 4; kc++) {
            uint32_t a[4][4], b[4][2];
#pragma unroll
            for (int mt = 0; mt < 4; mt++) {
                int r = wm * 64 + mt * 16 + g;
                int col = kc * 16 + 2 * tg;
                a[mt][0] = *(const uint32_t*)&sm.gm.A[r][col];
                a[mt][1] = *(const uint32_t*)&sm.gm.A[r + 8][col];
                a[mt][2] = *(const uint32_t*)&sm.gm.A[r][col + 8];
                a[mt][3] = *(const uint32_t*)&sm.gm.A[r + 8][col + 8];
            }
#pragma unroll
            for (int nt = 0; nt < 4; nt++) {
                int n = wn * 32 + nt * 8 + g;
                int kk = kc * 16 + 2 * tg;
                b[nt][0] = *(const uint32_t*)&sm.gm.B[n][kk];
                b[nt][1] = *(const uint32_t*)&sm.gm.B[n][kk + 8];
            }
#pragma unroll
            for (int mt = 0; mt < 4; mt++)
#pragma unroll
                for (int nt = 0; nt < 4; nt++)
                    mma16816(c[mt][nt], a[mt], b[nt][0], b[nt][1]);
        }
        __syncthreads();
    }

    const int bidx = m0 >> 11;
    const int s0   = m0 & 2047;

#pragma unroll
    for (int p = 0; p < 2; p++) {
        // warps with wn>>1 == p own cols [p*64, p*64+64)
        if ((wn >> 1) == p) {
#pragma unroll
            for (int mt = 0; mt < 4; mt++)
#pragma unroll
                for (int nt = 0; nt < 4; nt++) {
                    int r = wm * 64 + mt * 16 + g;
                    int col = (wn & 1) * 32 + nt * 8 + 2 * tg;
                    sm.epi[r][col]         = c[mt][nt][0];
                    sm.epi[r][col + 1]     = c[mt][nt][1];
                    sm.epi[r + 8][col]     = c[mt][nt][2];
                    sm.epi[r + 8][col + 1] = c[mt][nt][3];
                }
        }
        __syncthreads();

        const int nc = n0 + p * 64;

        if (EPI == 2) {
#pragma unroll 4
            for (int idx = tid; idx < 128 * 64; idx += 256) {
                int r = idx >> 6, i = idx & 63;
                outf[(size_t)(m0 + r) * 1024 + nc + i] = sm.epi[r][i] + bias[nc + i];
            }
        } else if (EPI == 1 && blockIdx.x >= 8) {
            // V half: no norm, TRANSPOSED write [bh][d][s]
            const int hv = (blockIdx.x - 8) * 2 + p;
            const size_t vbase = (size_t)(bidx * HH + hv) * 64;
#pragma unroll 4
            for (int idx = tid; idx < 128 * 64; idx += 256) {
                int d = idx >> 7, r = idx & 127;
                float v = sm.epi[r][d] + bias[nc + d];
                o1[(vbase + d) * 2048 + s0 + r] = __float2half_rn(v);
            }
        } else {
            if (tid < 128) {
                float ss = 0.f;
#pragma unroll 8
                for (int i = 0; i < 64; i++) {
                    float v = sm.epi[tid][i] + bias[nc + i];
                    ss += v * v;
                }
                invs[tid] = rsqrtf(ss * (1.0f / 64.0f) + 1e-6f);
            }
            __syncthreads();
            const int h = blockIdx.x * 2 + p;
            // EPI0: fold 1/sqrt(HD) AND log2(e) into q so attention can use raw ex2
            const float postmul = (EPI == 0) ? 0.125f * 1.4426950408889634f : 1.0f;
#pragma unroll 4
            for (int idx = tid; idx < 128 * 64; idx += 256) {
                int r = idx >> 6, i = idx & 63;
                float v = sm.epi[r][i] + bias[nc + i];
                float w = v * invs[r] * gvec[i] * postmul;
                o0[((size_t)(bidx * HH + h) * 2048 + s0 + r) * 64 + i] = __float2half_rn(w);
            }
        }
        __syncthreads();
    }
}

// ---------------- flash attention: 256 thr, 128 q-rows/CTA, 128-wide KV tiles ----------------
// Streaming softmax WITHOUT online max: scores (log2 domain) bounded by
// |s| <= ||q||*||k||*log2e = 8*1.4427 = 11.54, so 2^s <= 2981: f32-safe sums,
// fp16-safe P. S processed in two 8-nt halves to cap live registers (<=128)
// enabling 2 CTAs/SM for latency hiding.
#define ATT_KS 18432    // K tile: 128 rows x 72 halves
#define ATT_VS 17408    // V tile: 64 rows x 136 halves
#define ATT_STG (ATT_KS + ATT_VS)
#define ATT_SMEM (2*ATT_STG)

__global__ __launch_bounds__(256, 2) void attn_kernel(
    const __half* __restrict__ Q,
    const __half* __restrict__ K,
    const __half* __restrict__ Vt,
    __half* __restrict__ O)
{
    extern __shared__ __align__(16) char dynsmem[];
    const uint32_t sbase = (uint32_t)__cvta_generic_to_shared(dynsmem);

    const int tid = threadIdx.x, w = tid >> 5, lane = tid & 31;
    const int g = lane >> 2, tg = lane & 3;
    const int qt = blockIdx.x, h = blockIdx.y, b = blockIdx.z;
    const int bh = b * HH + h;

    const size_t koff = (size_t)bh * SS * 64;
    const size_t voff = (size_t)bh * 64 * 2048;
    const size_t qoff = koff + (size_t)qt * 128 * 64;

    // Q fragments direct from gmem (once per CTA)
    uint32_t aq[4][4];
    {
        const __half* qg = Q + qoff;
        int r = w * 16 + g;
#pragma unroll
        for (int kc = 0; kc < 4; kc++) {
            int col = kc * 16 + 2 * tg;
            aq[kc][0] = *(const uint32_t*)(qg + r * 64 + col);
            aq[kc][1] = *(const uint32_t*)(qg + (r + 8) * 64 + col);
            aq[kc][2] = *(const uint32_t*)(qg + r * 64 + col + 8);
            aq[kc][3] = *(const uint32_t*)(qg + (r + 8) * 64 + col + 8);
        }
    }

    float oacc[8][4];
#pragma unroll
    for (int nt = 0; nt < 8; nt++)
#pragma unroll
        for (int i = 0; i < 4; i++) oacc[nt][i] = 0.f;
    float lrow0 = 0.f, lrow1 = 0.f;

    // tile j covers kv rows [j*128, j*128+128)
    auto issue = [&](int j, int st) {
        uint32_t sb = sbase + st * ATT_STG;
        // K tile: 128 rows x 64 d, 4 chunks/thread
#pragma unroll
        for (int t = 0; t < 4; t++) {
            int row = (tid >> 3) + t * 32;
            int col = (tid & 7) * 8;
            cpa16(sb + row * 144 + col * 2, K + koff + j * 8192 + row * 64 + col);
        }
        // V tile (transposed): 64 d-rows x 128 t, 4 chunks/thread
#pragma unroll
        for (int t = 0; t < 4; t++) {
            int d = (tid >> 4) + t * 16;
            int cl = (tid & 15) * 8;
            cpa16(sb + ATT_KS + d * 272 + cl * 2, Vt + voff + (size_t)d * 2048 + j * 128 + cl);
        }
    };

    issue(0, 0);
    asm volatile("cp.async.commit_group;\n");

    for (int j = 0; j < SS / 128; j++) {
        int st = j & 1;
        if (j + 1 < SS / 128) issue(j + 1, st ^ 1);
        asm volatile("cp.async.commit_group;\n");
        asm volatile("cp.async.wait_group 1;\n");
        __syncthreads();

        __half (*ks)[72]  = (__half(*)[72])(dynsmem + st * ATT_STG);
        __half (*vs)[136] = (__half(*)[136])(dynsmem + st * ATT_STG + ATT_KS);

        // S = q @ k^T processed in two halves of 8 nt-tiles each to cap live regs
        uint32_t pa[8][4];
        float ps0 = 0.f, ps1 = 0.f;
#pragma unroll
        for (int hf = 0; hf < 2; hf++) {
            float sf[8][4];
#pragma unroll
            for (int nt = 0; nt < 8; nt++) {
#pragma unroll
                for (int i = 0; i < 4; i++) sf[nt][i] = 0.f;
#pragma unroll
                for (int kc = 0; kc < 4; kc++) {
                    int col = kc * 16 + 2 * tg;
                    int rr = (hf * 8 + nt) * 8 + g;
                    uint32_t b0 = *(const uint32_t*)&ks[rr][col];
                    uint32_t b1 = *(const uint32_t*)&ks[rr][col + 8];
                    mma16816(sf[nt], aq[kc], b0, b1);
                }
            }
            // scores already in log2 domain: raw ex2
#pragma unroll
            for (int nt = 0; nt < 8; nt++) {
                sf[nt][0] = ex2f(sf[nt][0]);
                sf[nt][1] = ex2f(sf[nt][1]);
                sf[nt][2] = ex2f(sf[nt][2]);
                sf[nt][3] = ex2f(sf[nt][3]);
                ps0 += sf[nt][0] + sf[nt][1];
                ps1 += sf[nt][2] + sf[nt][3];
            }
#pragma unroll
            for (int kcl = 0; kcl < 4; kcl++) {
                pa[hf * 4 + kcl][0] = packh2(sf[2 * kcl][0],     sf[2 * kcl][1]);
                pa[hf * 4 + kcl][1] = packh2(sf[2 * kcl][2],     sf[2 * kcl][3]);
                pa[hf * 4 + kcl][2] = packh2(sf[2 * kcl + 1][0], sf[2 * kcl + 1][1]);
                pa[hf * 4 + kcl][3] = packh2(sf[2 * kcl + 1][2], sf[2 * kcl + 1][3]);
            }
        }
        lrow0 += ps0;
        lrow1 += ps1;

        // O += P @ V (no rescale needed)
#pragma unroll
        for (int nt = 0; nt < 8; nt++) {
            int d = nt * 8 + g;
#pragma unroll
            for (int kc = 0; kc < 8; kc++) {
                int t0 = kc * 16 + 2 * tg;
                uint32_t b0 = *(const uint32_t*)&vs[d][t0];
                uint32_t b1 = *(const uint32_t*)&vs[d][t0 + 8];
                mma16816(oacc[nt], pa[kc], b0, b1);
            }
        }
        __syncthreads();
    }

    lrow0 += __shfl_xor_sync(0xffffffffu, lrow0, 1);
    lrow0 += __shfl_xor_sync(0xffffffffu, lrow0, 2);
    lrow1 += __shfl_xor_sync(0xffffffffu, lrow1, 1);
    lrow1 += __shfl_xor_sync(0xffffffffu, lrow1, 2);
    float i0 = 1.f / lrow0;
    float i1 = 1.f / lrow1;

    const int srow = qt * 128 + w * 16 + g;
    size_t base = ((size_t)b * SS + srow) * 1024 + h * 64;
#pragma unroll
    for (int nt = 0; nt < 8; nt++) {
        int col = nt * 8 + 2 * tg;
        *(uint32_t*)(O + base + col)            = packh2(oacc[nt][0] * i0, oacc[nt][1] * i0);
        *(uint32_t*)(O + base + 8 * 1024 + col) = packh2(oacc[nt][2] * i1, oacc[nt][3] * i1);
    }
}

extern "C" void kernel_launch(void* const* d_in, const int* in_sizes, int n_in,
                              void* d_out, int out_size)
{
    const float* x     = (const float*)d_in[0];
    const float* ctx   = (const float*)d_in[1];
    const float* Wq    = (const float*)d_in[2];
    const float* bq    = (const float*)d_in[3];
    const float* Wkv   = (const float*)d_in[4];
    const float* bkv   = (const float*)d_in[5];
    const float* Wproj = (const float*)d_in[6];
    const float* bproj = (const float*)d_in[7];
    const float* gq    = (const float*)d_in[8];
    const float* gk    = (const float*)d_in[9];

    __half *xh, *ch, *wqh, *wkh, *wph, *qh, *kh, *vth, *aoh;
    cudaGetSymbolAddress((void**)&xh,  g_x);
    cudaGetSymbolAddress((void**)&ch,  g_c);
    cudaGetSymbolAddress((void**)&wqh, g_Wq);
    cudaGetSymbolAddress((void**)&wkh, g_Wk);
    cudaGetSymbolAddress((void**)&wph, g_Wp);
    cudaGetSymbolAddress((void**)&qh,  g_q);
    cudaGetSymbolAddress((void**)&kh,  g_k);
    cudaGetSymbolAddress((void**)&vth, g_vt);
    cudaGetSymbolAddress((void**)&aoh, g_ao);

    cudaFuncSetAttribute(attn_kernel, cudaFuncAttributeMaxDynamicSharedMemorySize, ATT_SMEM);

    f2h_kernel<<<MR * DD / 1024, 256>>>(x,   xh, MR * DD);
    f2h_kernel<<<MR * DD / 1024, 256>>>(ctx, ch, MR * DD);
    f2h_T_kernel<<<dim3(32, 32), 256>>>(Wq,    wqh, 1024, 1024);
    f2h_T_kernel<<<dim3(64, 32), 256>>>(Wkv,   wkh, 1024, 2048);
    f2h_T_kernel<<<dim3(32, 32), 256>>>(Wproj, wph, 1024, 1024);

    gemm_epi<0><<<dim3(8, 64), 256>>>(xh, wqh, bq, gq, qh, nullptr, nullptr);
    gemm_epi<1><<<dim3(16, 64), 256>>>(ch, wkh, bkv, gk, kh, vth, nullptr);
    attn_kernel<<<dim3(16, 16, 4), 256, ATT_SMEM>>>(qh, kh, vth, aoh);
    gemm_epi<2><<<dim3(8, 64), 256>>>(aoh, wph, bproj, nullptr, nullptr, nullptr, (float*)d_out);
}